// round 2
// baseline (speedup 1.0000x reference)
#include <cuda_runtime.h>
#include <cuda_bf16.h>
#include <math.h>

// ---------------------------------------------------------------------------
// Problem constants
// ---------------------------------------------------------------------------
#define T_SEQ    2048
#define D_MODEL  2048
#define N_HEADS  32
#define N_KV     8
#define HEAD_DIM 64
#define KV_DIM   (N_KV * HEAD_DIM)     // 512
#define WINDOW_HALF 256                // rows keep cols [i-256, i+256)

// ---------------------------------------------------------------------------
// Scratch (device globals; no allocation allowed)
// ---------------------------------------------------------------------------
__device__ float g_Q[(size_t)T_SEQ * D_MODEL];     // 16 MB
__device__ float g_K[(size_t)T_SEQ * KV_DIM];      // 4 MB
__device__ float g_V[(size_t)T_SEQ * KV_DIM];      // 4 MB
__device__ float g_O[(size_t)T_SEQ * D_MODEL];     // 16 MB
__device__ float g_cos[T_SEQ * 32];
__device__ float g_sin[T_SEQ * 32];

// ---------------------------------------------------------------------------
// Tensor-core tf32 GEMM with 3xTF32 split (fp32-accurate).
//   C[M,N] = A[M,K] * B[N,K]^T   (row-major, K-contig)
// Block 128x128x16, 256 threads = 8 warps (2x4), warp tile 64x32.
// mma.sync.aligned.m16n8k8.row.col.f32.tf32.tf32.f32
// ---------------------------------------------------------------------------
#define BM 128
#define BN 128
#define BK 16
#define SPAD 132   // smem row stride (K-major tiles [BK][SPAD])

__device__ __forceinline__ void mma_tf32(float* c, const unsigned* a, const unsigned* b)
{
    asm volatile(
        "mma.sync.aligned.m16n8k8.row.col.f32.tf32.tf32.f32 "
        "{%0,%1,%2,%3}, {%4,%5,%6,%7}, {%8,%9}, {%0,%1,%2,%3};"
        : "+f"(c[0]), "+f"(c[1]), "+f"(c[2]), "+f"(c[3])
        : "r"(a[0]), "r"(a[1]), "r"(a[2]), "r"(a[3]),
          "r"(b[0]), "r"(b[1]));
}

__device__ __forceinline__ void split_tf32(float x, unsigned& hi, unsigned& lo)
{
    unsigned h;
    asm("cvt.rna.tf32.f32 %0, %1;" : "=r"(h) : "f"(x));
    float r = x - __uint_as_float(h);
    asm("cvt.rna.tf32.f32 %0, %1;" : "=r"(lo) : "f"(r));
    hi = h;
}

__global__ void __launch_bounds__(256)
gemm_tf32(const float* __restrict__ A, const float* __restrict__ B,
          float* __restrict__ C, int M, int N, int K)
{
    __shared__ float As[BK][SPAD];
    __shared__ float Bs[BK][SPAD];

    const int tid = threadIdx.x;
    const int bm = blockIdx.y * BM;
    const int bn = blockIdx.x * BN;

    const int warp = tid >> 5;
    const int lane = tid & 31;
    const int qr = lane >> 2;      // 0..7
    const int qc = lane & 3;       // 0..3
    const int wr = warp >> 2;      // 0..1  -> 64-row slab
    const int wc = warp & 3;       // 0..3  -> 32-col slab

    const int loadRow = tid >> 2;          // 0..63
    const int loadCol = (tid & 3) * 4;     // 0,4,8,12

    float acc[4][4][4];   // [mtile][ntile][reg]
#pragma unroll
    for (int i = 0; i < 4; i++)
#pragma unroll
        for (int j = 0; j < 4; j++)
#pragma unroll
            for (int r = 0; r < 4; r++) acc[i][j][r] = 0.f;

    for (int k0 = 0; k0 < K; k0 += BK) {
        // stage fp32 tiles, K-major in smem
#pragma unroll
        for (int it = 0; it < 2; it++) {
            const int r = loadRow + it * 64;
            float4 va = *(const float4*)(A + (size_t)(bm + r) * K + k0 + loadCol);
            As[loadCol + 0][r] = va.x;
            As[loadCol + 1][r] = va.y;
            As[loadCol + 2][r] = va.z;
            As[loadCol + 3][r] = va.w;
            float4 vb = *(const float4*)(B + (size_t)(bn + r) * K + k0 + loadCol);
            Bs[loadCol + 0][r] = vb.x;
            Bs[loadCol + 1][r] = vb.y;
            Bs[loadCol + 2][r] = vb.z;
            Bs[loadCol + 3][r] = vb.w;
        }
        __syncthreads();

#pragma unroll
        for (int ks = 0; ks < BK; ks += 8) {
            unsigned ah[4][4], al[4][4];   // [mtile][reg]
            unsigned bh[4][2], bl[4][2];   // [ntile][reg]
#pragma unroll
            for (int mt = 0; mt < 4; mt++) {
                const int rbase = wr * 64 + mt * 16 + qr;
                split_tf32(As[ks + qc    ][rbase    ], ah[mt][0], al[mt][0]);
                split_tf32(As[ks + qc    ][rbase + 8], ah[mt][1], al[mt][1]);
                split_tf32(As[ks + qc + 4][rbase    ], ah[mt][2], al[mt][2]);
                split_tf32(As[ks + qc + 4][rbase + 8], ah[mt][3], al[mt][3]);
            }
#pragma unroll
            for (int nt = 0; nt < 4; nt++) {
                const int nbase = wc * 32 + nt * 8 + qr;
                split_tf32(Bs[ks + qc    ][nbase], bh[nt][0], bl[nt][0]);
                split_tf32(Bs[ks + qc + 4][nbase], bh[nt][1], bl[nt][1]);
            }
#pragma unroll
            for (int mt = 0; mt < 4; mt++)
#pragma unroll
                for (int nt = 0; nt < 4; nt++) {
                    mma_tf32(acc[mt][nt], ah[mt], bh[nt]);
                    mma_tf32(acc[mt][nt], ah[mt], bl[nt]);
                    mma_tf32(acc[mt][nt], al[mt], bh[nt]);
                }
        }
        __syncthreads();
    }

    // epilogue: c0,c1 -> (qr, 2qc, 2qc+1); c2,c3 -> (qr+8, ...)
#pragma unroll
    for (int mt = 0; mt < 4; mt++) {
        const int row0 = bm + wr * 64 + mt * 16 + qr;
#pragma unroll
        for (int nt = 0; nt < 4; nt++) {
            const int col = bn + wc * 32 + nt * 8 + qc * 2;
            *(float2*)(C + (size_t)row0       * N + col) = make_float2(acc[mt][nt][0], acc[mt][nt][1]);
            *(float2*)(C + (size_t)(row0 + 8) * N + col) = make_float2(acc[mt][nt][2], acc[mt][nt][3]);
        }
    }
}

// ---------------------------------------------------------------------------
// RoPE tables: cos/sin(t * 10000^{-i/32}) with double-precision angle
// reduction (safe under fast-math; args up to 2048 rad otherwise).
// ---------------------------------------------------------------------------
__global__ void rope_tables()
{
    int idx = blockIdx.x * blockDim.x + threadIdx.x;   // 0 .. T*32-1
    if (idx >= T_SEQ * 32) return;
    int i = idx & 31;
    int t = idx >> 5;
    double invf = exp2(-(double)i / 32.0 * 13.287712379549449392);
    double ang  = fmod((double)t * invf, 6.28318530717958647692);
    g_cos[idx] = cosf((float)ang);
    g_sin[idx] = sinf((float)ang);
}

__global__ void rope_apply(float* __restrict__ X, int nheads)
{
    int idx = blockIdx.x * blockDim.x + threadIdx.x;
    int total = T_SEQ * nheads * 32;
    if (idx >= total) return;
    int i = idx & 31;
    int h = (idx >> 5) % nheads;
    int t = idx / (32 * nheads);
    float c = g_cos[t * 32 + i];
    float s = g_sin[t * 32 + i];
    float* row = X + (size_t)t * (nheads * HEAD_DIM) + h * HEAD_DIM;
    float x0 = row[i];
    float x1 = row[i + 32];
    row[i]      = x0 * c - x1 * s;
    row[i + 32] = x1 * c + x0 * s;
}

// ---------------------------------------------------------------------------
// Banded GQA attention. One warp per query row; 16 queries (one head) per
// block. K/V streamed through smem in chunks of 64 keys. Scores are bounded
// (|s| < ~8) so softmax needs no max subtraction.
// ---------------------------------------------------------------------------
#define TQ 16      // queries per block (= warps per block)
#define CH 64      // kv chunk

__global__ void __launch_bounds__(TQ * 32)
attn_kernel(const float* __restrict__ Q, const float* __restrict__ K,
            const float* __restrict__ V, float* __restrict__ O)
{
    __shared__ float Kst[CH][CH + 1];  // transposed: [d][j], padded
    __shared__ float Vs[CH][CH];       // [j][d]

    const int h  = blockIdx.y;
    const int g  = h >> 2;                 // kv head
    const int i0 = blockIdx.x * TQ;
    const int w  = threadIdx.x >> 5;
    const int l  = threadIdx.x & 31;
    const int i  = i0 + w;                 // this warp's query row

    const float q0 = Q[(size_t)i * D_MODEL + h * HEAD_DIM + l];
    const float q1 = Q[(size_t)i * D_MODEL + h * HEAD_DIM + 32 + l];

    float o0 = 0.f, o1 = 0.f, ssum = 0.f;

    const int jlo = max(0, i - WINDOW_HALF);
    const int jhi = min(T_SEQ, i + WINDOW_HALF);

    const int jstart = max(0, i0 - WINDOW_HALF);
    const int jend   = min(T_SEQ, i0 + TQ - 1 + WINDOW_HALF);

    for (int c = jstart; c < jend; c += CH) {
        __syncthreads();
#pragma unroll
        for (int it = 0; it < 2; it++) {
            int idx = threadIdx.x + it * (TQ * 32);   // 0..1023
            int j  = idx >> 4;
            int d4 = (idx & 15) * 4;
            int ja = c + j;
            float4 kv, vv;
            if (ja < T_SEQ) {
                kv = *(const float4*)(K + (size_t)ja * KV_DIM + g * HEAD_DIM + d4);
                vv = *(const float4*)(V + (size_t)ja * KV_DIM + g * HEAD_DIM + d4);
            } else {
                kv = make_float4(0.f, 0.f, 0.f, 0.f);
                vv = kv;
            }
            Kst[d4 + 0][j] = kv.x;
            Kst[d4 + 1][j] = kv.y;
            Kst[d4 + 2][j] = kv.z;
            Kst[d4 + 3][j] = kv.w;
            *(float4*)&Vs[j][d4] = vv;
        }
        __syncthreads();

        float s0 = 0.f, s1 = 0.f;
#pragma unroll
        for (int d = 0; d < 32; d++) {
            float qa = __shfl_sync(0xffffffffu, q0, d);
            s0 = fmaf(qa, Kst[d][l],      s0);
            s1 = fmaf(qa, Kst[d][l + 32], s1);
        }
#pragma unroll
        for (int d = 0; d < 32; d++) {
            float qa = __shfl_sync(0xffffffffu, q1, d);
            s0 = fmaf(qa, Kst[32 + d][l],      s0);
            s1 = fmaf(qa, Kst[32 + d][l + 32], s1);
        }
        const int ja0 = c + l, ja1 = c + l + 32;
        float p0 = (ja0 >= jlo && ja0 < jhi) ? __expf(s0 * 0.125f) : 0.f;
        float p1 = (ja1 >= jlo && ja1 < jhi) ? __expf(s1 * 0.125f) : 0.f;
        ssum += p0 + p1;

#pragma unroll
        for (int j = 0; j < 32; j++) {
            float pa = __shfl_sync(0xffffffffu, p0, j);
            o0 = fmaf(pa, Vs[j][l],      o0);
            o1 = fmaf(pa, Vs[j][l + 32], o1);
            float pb = __shfl_sync(0xffffffffu, p1, j);
            o0 = fmaf(pb, Vs[j + 32][l],      o0);
            o1 = fmaf(pb, Vs[j + 32][l + 32], o1);
        }
    }

#pragma unroll
    for (int off = 16; off; off >>= 1)
        ssum += __shfl_xor_sync(0xffffffffu, ssum, off);
    const float inv = 1.f / ssum;

    O[(size_t)i * D_MODEL + h * HEAD_DIM + l]      = o0 * inv;
    O[(size_t)i * D_MODEL + h * HEAD_DIM + 32 + l] = o1 * inv;
}

// ---------------------------------------------------------------------------
// Launch
// ---------------------------------------------------------------------------
extern "C" void kernel_launch(void* const* d_in, const int* in_sizes, int n_in,
                              void* d_out, int out_size)
{
    const float* X  = (const float*)d_in[0];
    const float* Wq = (const float*)d_in[1];
    const float* Wk = (const float*)d_in[2];
    const float* Wv = (const float*)d_in[3];
    const float* Wo = (const float*)d_in[4];
    float* out = (float*)d_out;

    float* Qb;  cudaGetSymbolAddress((void**)&Qb, g_Q);
    float* Kb;  cudaGetSymbolAddress((void**)&Kb, g_K);
    float* Vb;  cudaGetSymbolAddress((void**)&Vb, g_V);
    float* Ob;  cudaGetSymbolAddress((void**)&Ob, g_O);

    rope_tables<<<(T_SEQ * 32 + 255) / 256, 256>>>();

    gemm_tf32<<<dim3(D_MODEL / BN, T_SEQ / BM), 256>>>(X, Wq, Qb, T_SEQ, D_MODEL, D_MODEL);
    gemm_tf32<<<dim3(KV_DIM  / BN, T_SEQ / BM), 256>>>(X, Wk, Kb, T_SEQ, KV_DIM,  D_MODEL);
    gemm_tf32<<<dim3(KV_DIM  / BN, T_SEQ / BM), 256>>>(X, Wv, Vb, T_SEQ, KV_DIM,  D_MODEL);

    rope_apply<<<(T_SEQ * N_HEADS * 32 + 255) / 256, 256>>>(Qb, N_HEADS);
    rope_apply<<<(T_SEQ * N_KV    * 32 + 255) / 256, 256>>>(Kb, N_KV);

    attn_kernel<<<dim3(T_SEQ / TQ, N_HEADS), TQ * 32>>>(Qb, Kb, Vb, Ob);

    gemm_tf32<<<dim3(D_MODEL / BN, T_SEQ / BM), 256>>>(Ob, Wo, out, T_SEQ, D_MODEL, D_MODEL);
}

// round 3
// speedup vs baseline: 1.2162x; 1.2162x over previous
#include <cuda_runtime.h>
#include <cuda_bf16.h>
#include <math.h>

// ---------------------------------------------------------------------------
// Problem constants
// ---------------------------------------------------------------------------
#define T_SEQ    2048
#define D_MODEL  2048
#define N_HEADS  32
#define N_KV     8
#define HEAD_DIM 64
#define KV_DIM   (N_KV * HEAD_DIM)     // 512
#define QKV_N    (D_MODEL + 2 * KV_DIM)  // 3072
#define WINDOW_HALF 256

// ---------------------------------------------------------------------------
// Scratch (device globals; no allocation allowed)
// ---------------------------------------------------------------------------
__device__ float  g_Q[(size_t)T_SEQ * D_MODEL];      // 16 MB
__device__ float  g_K[(size_t)T_SEQ * KV_DIM];       // 4 MB
__device__ float  g_V[(size_t)T_SEQ * KV_DIM];       // 4 MB
__device__ float  g_O[(size_t)T_SEQ * D_MODEL];      // 16 MB
__device__ float2 g_X2[(size_t)T_SEQ * D_MODEL];     // 32 MB  (hi,lo tf32 planes)
__device__ float2 g_Wqkv2[(size_t)QKV_N * D_MODEL];  // 48 MB
__device__ float2 g_Wo2[(size_t)D_MODEL * D_MODEL];  // 32 MB
__device__ float2 g_O2[(size_t)T_SEQ * D_MODEL];     // 32 MB
__device__ float  g_cos[T_SEQ * 32];
__device__ float  g_sin[T_SEQ * 32];

// ---------------------------------------------------------------------------
// tf32 helpers
// ---------------------------------------------------------------------------
__device__ __forceinline__ unsigned cvt_tf32(float x)
{
    unsigned r;
    asm("cvt.rna.tf32.f32 %0, %1;" : "=r"(r) : "f"(x));
    return r;
}

__device__ __forceinline__ void mma_tf32(float* c, const unsigned* a, const unsigned* b)
{
    asm volatile(
        "mma.sync.aligned.m16n8k8.row.col.f32.tf32.tf32.f32 "
        "{%0,%1,%2,%3}, {%4,%5,%6,%7}, {%8,%9}, {%0,%1,%2,%3};"
        : "+f"(c[0]), "+f"(c[1]), "+f"(c[2]), "+f"(c[3])
        : "r"(a[0]), "r"(a[1]), "r"(a[2]), "r"(a[3]),
          "r"(b[0]), "r"(b[1]));
}

// ---------------------------------------------------------------------------
// Split fp32 -> interleaved (hi, lo) tf32 planes. n4 = count/4.
// ---------------------------------------------------------------------------
__global__ void split2(const float* __restrict__ s, float2* __restrict__ d, int n4)
{
    int i = blockIdx.x * blockDim.x + threadIdx.x;
    if (i >= n4) return;
    float4 v = ((const float4*)s)[i];
    float x[4] = {v.x, v.y, v.z, v.w};
    float2 o[4];
#pragma unroll
    for (int j = 0; j < 4; j++) {
        float hf = __uint_as_float(cvt_tf32(x[j]));
        float lf = __uint_as_float(cvt_tf32(x[j] - hf));
        o[j] = make_float2(hf, lf);
    }
    float4* dd = (float4*)(d + (size_t)i * 4);
    dd[0] = make_float4(o[0].x, o[0].y, o[1].x, o[1].y);
    dd[1] = make_float4(o[2].x, o[2].y, o[3].x, o[3].y);
}

// ---------------------------------------------------------------------------
// Pipelined tensor-core GEMM on pre-split operands.
//   C[M,N] = A[M,K] * B[N,K]^T, A2/B2 are float2 (hi,lo) planes, K-contig.
// Block 128x128x16, 256 threads (8 warps, warp tile 64x32), 2-stage cp.async.
// Output routed to up to 3 regions by absolute column (fused QKV).
// ---------------------------------------------------------------------------
#define BM 128
#define BN 128
#define BK 16
#define SPAD2 18                     // float2 per smem row (16 + pad), 16B-aligned
#define TILE_F2 (128 * SPAD2)        // float2 per tile per stage
#define STG_BYTES (TILE_F2 * 8)      // bytes per tile per stage
#define GEMM_SMEM (4 * STG_BYTES)    // 2 stages x (A + B) = 73728 B

__device__ __forceinline__ void cp16(unsigned dst, const void* src)
{
    asm volatile("cp.async.ca.shared.global [%0], [%1], 16;" :: "r"(dst), "l"(src));
}

__device__ __forceinline__ void stage_tiles(unsigned sA, unsigned sB,
                                            const float2* A2, const float2* B2,
                                            int K, int bm, int bn, int k0, int tid)
{
#pragma unroll
    for (int t = 0; t < 4; t++) {
        int id  = tid + t * 256;       // 0..1023
        int row = id >> 3;             // 0..127
        int cp  = (id & 7) * 2;        // float2 offset within 16-k row
        unsigned soff = (unsigned)(row * SPAD2 + cp) * 8u;
        cp16(sA + soff, A2 + (size_t)(bm + row) * K + k0 + cp);
        cp16(sB + soff, B2 + (size_t)(bn + row) * K + k0 + cp);
    }
}

__global__ void __launch_bounds__(256)
gemm_split(const float2* __restrict__ A2, const float2* __restrict__ B2,
           int M, int N, int K,
           float* __restrict__ C0, int n0, int s0,
           float* __restrict__ C1, int n1, int s1,
           float* __restrict__ C2, int s2)
{
    extern __shared__ float2 sm[];
    float2* As = sm;                    // [2][TILE_F2]
    float2* Bs = sm + 2 * TILE_F2;
    unsigned sAu = (unsigned)__cvta_generic_to_shared(As);
    unsigned sBu = (unsigned)__cvta_generic_to_shared(Bs);

    const int tid = threadIdx.x;
    const int bm = blockIdx.y * BM;
    const int bn = blockIdx.x * BN;

    const int warp = tid >> 5;
    const int lane = tid & 31;
    const int qr = lane >> 2;
    const int qc = lane & 3;
    const int wr = warp >> 2;       // 0..1
    const int wc = warp & 3;        // 0..3

    float acc[4][4][4];
#pragma unroll
    for (int i = 0; i < 4; i++)
#pragma unroll
        for (int j = 0; j < 4; j++)
#pragma unroll
            for (int r = 0; r < 4; r++) acc[i][j][r] = 0.f;

    const int NS = K / BK;

    stage_tiles(sAu, sBu, A2, B2, K, bm, bn, 0, tid);
    asm volatile("cp.async.commit_group;" ::: "memory");
    stage_tiles(sAu + STG_BYTES, sBu + STG_BYTES, A2, B2, K, bm, bn, BK, tid);
    asm volatile("cp.async.commit_group;" ::: "memory");

    for (int s = 0; s < NS; s++) {
        asm volatile("cp.async.wait_group 1;" ::: "memory");
        __syncthreads();

        const int buf = s & 1;
        const float2* At = As + buf * TILE_F2;
        const float2* Bt = Bs + buf * TILE_F2;

#pragma unroll
        for (int ks = 0; ks < BK; ks += 8) {
            float2 a[4][4], b[4][2];
#pragma unroll
            for (int mt = 0; mt < 4; mt++) {
                const int r = wr * 64 + mt * 16 + qr;
                a[mt][0] = At[r * SPAD2 + ks + qc];
                a[mt][1] = At[(r + 8) * SPAD2 + ks + qc];
                a[mt][2] = At[r * SPAD2 + ks + qc + 4];
                a[mt][3] = At[(r + 8) * SPAD2 + ks + qc + 4];
            }
#pragma unroll
            for (int nt = 0; nt < 4; nt++) {
                const int n = wc * 32 + nt * 8 + qr;
                b[nt][0] = Bt[n * SPAD2 + ks + qc];
                b[nt][1] = Bt[n * SPAD2 + ks + qc + 4];
            }
#pragma unroll
            for (int mt = 0; mt < 4; mt++) {
                unsigned ah[4], al[4];
#pragma unroll
                for (int r = 0; r < 4; r++) {
                    ah[r] = __float_as_uint(a[mt][r].x);
                    al[r] = __float_as_uint(a[mt][r].y);
                }
#pragma unroll
                for (int nt = 0; nt < 4; nt++) {
                    unsigned bh[2] = {__float_as_uint(b[nt][0].x), __float_as_uint(b[nt][1].x)};
                    unsigned bl[2] = {__float_as_uint(b[nt][0].y), __float_as_uint(b[nt][1].y)};
                    mma_tf32(acc[mt][nt], ah, bh);
                    mma_tf32(acc[mt][nt], ah, bl);
                    mma_tf32(acc[mt][nt], al, bh);
                }
            }
        }
        __syncthreads();

        if (s + 2 < NS)
            stage_tiles(sAu + buf * STG_BYTES, sBu + buf * STG_BYTES,
                        A2, B2, K, bm, bn, (s + 2) * BK, tid);
        asm volatile("cp.async.commit_group;" ::: "memory");
    }

    // route output region by absolute column
    float* C; int col0, stride;
    if (bn < n0)      { C = C0; col0 = bn;      stride = s0; }
    else if (bn < n1) { C = C1; col0 = bn - n0; stride = s1; }
    else              { C = C2; col0 = bn - n1; stride = s2; }

#pragma unroll
    for (int mt = 0; mt < 4; mt++) {
        const int row0 = bm + wr * 64 + mt * 16 + qr;
#pragma unroll
        for (int nt = 0; nt < 4; nt++) {
            const int col = col0 + wc * 32 + nt * 8 + qc * 2;
            *(float2*)(C + (size_t)row0       * stride + col) = make_float2(acc[mt][nt][0], acc[mt][nt][1]);
            *(float2*)(C + (size_t)(row0 + 8) * stride + col) = make_float2(acc[mt][nt][2], acc[mt][nt][3]);
        }
    }
}

// ---------------------------------------------------------------------------
// RoPE
// ---------------------------------------------------------------------------
__global__ void rope_tables()
{
    int idx = blockIdx.x * blockDim.x + threadIdx.x;
    if (idx >= T_SEQ * 32) return;
    int i = idx & 31;
    int t = idx >> 5;
    double invf = exp2(-(double)i / 32.0 * 13.287712379549449392);
    double ang  = fmod((double)t * invf, 6.28318530717958647692);
    g_cos[idx] = cosf((float)ang);
    g_sin[idx] = sinf((float)ang);
}

__global__ void rope_apply(float* __restrict__ X, int nheads)
{
    int idx = blockIdx.x * blockDim.x + threadIdx.x;
    int total = T_SEQ * nheads * 32;
    if (idx >= total) return;
    int i = idx & 31;
    int h = (idx >> 5) % nheads;
    int t = idx / (32 * nheads);
    float c = g_cos[t * 32 + i];
    float s = g_sin[t * 32 + i];
    float* row = X + (size_t)t * (nheads * HEAD_DIM) + h * HEAD_DIM;
    float x0 = row[i];
    float x1 = row[i + 32];
    row[i]      = x0 * c - x1 * s;
    row[i + 32] = x1 * c + x0 * s;
}

// ---------------------------------------------------------------------------
// Banded GQA attention (unchanged from passing round-1 kernel)
// ---------------------------------------------------------------------------
#define TQ 16
#define CH 64

__global__ void __launch_bounds__(TQ * 32)
attn_kernel(const float* __restrict__ Q, const float* __restrict__ K,
            const float* __restrict__ V, float* __restrict__ O)
{
    __shared__ float Kst[CH][CH + 1];
    __shared__ float Vs[CH][CH];

    const int h  = blockIdx.y;
    const int g  = h >> 2;
    const int i0 = blockIdx.x * TQ;
    const int w  = threadIdx.x >> 5;
    const int l  = threadIdx.x & 31;
    const int i  = i0 + w;

    const float q0 = Q[(size_t)i * D_MODEL + h * HEAD_DIM + l];
    const float q1 = Q[(size_t)i * D_MODEL + h * HEAD_DIM + 32 + l];

    float o0 = 0.f, o1 = 0.f, ssum = 0.f;

    const int jlo = max(0, i - WINDOW_HALF);
    const int jhi = min(T_SEQ, i + WINDOW_HALF);

    const int jstart = max(0, i0 - WINDOW_HALF);
    const int jend   = min(T_SEQ, i0 + TQ - 1 + WINDOW_HALF);

    for (int c = jstart; c < jend; c += CH) {
        __syncthreads();
#pragma unroll
        for (int it = 0; it < 2; it++) {
            int idx = threadIdx.x + it * (TQ * 32);
            int j  = idx >> 4;
            int d4 = (idx & 15) * 4;
            int ja = c + j;
            float4 kv, vv;
            if (ja < T_SEQ) {
                kv = *(const float4*)(K + (size_t)ja * KV_DIM + g * HEAD_DIM + d4);
                vv = *(const float4*)(V + (size_t)ja * KV_DIM + g * HEAD_DIM + d4);
            } else {
                kv = make_float4(0.f, 0.f, 0.f, 0.f);
                vv = kv;
            }
            Kst[d4 + 0][j] = kv.x;
            Kst[d4 + 1][j] = kv.y;
            Kst[d4 + 2][j] = kv.z;
            Kst[d4 + 3][j] = kv.w;
            *(float4*)&Vs[j][d4] = vv;
        }
        __syncthreads();

        float s0 = 0.f, s1 = 0.f;
#pragma unroll
        for (int d = 0; d < 32; d++) {
            float qa = __shfl_sync(0xffffffffu, q0, d);
            s0 = fmaf(qa, Kst[d][l],      s0);
            s1 = fmaf(qa, Kst[d][l + 32], s1);
        }
#pragma unroll
        for (int d = 0; d < 32; d++) {
            float qa = __shfl_sync(0xffffffffu, q1, d);
            s0 = fmaf(qa, Kst[32 + d][l],      s0);
            s1 = fmaf(qa, Kst[32 + d][l + 32], s1);
        }
        const int ja0 = c + l, ja1 = c + l + 32;
        float p0 = (ja0 >= jlo && ja0 < jhi) ? __expf(s0 * 0.125f) : 0.f;
        float p1 = (ja1 >= jlo && ja1 < jhi) ? __expf(s1 * 0.125f) : 0.f;
        ssum += p0 + p1;

#pragma unroll
        for (int j = 0; j < 32; j++) {
            float pa = __shfl_sync(0xffffffffu, p0, j);
            o0 = fmaf(pa, Vs[j][l],      o0);
            o1 = fmaf(pa, Vs[j][l + 32], o1);
            float pb = __shfl_sync(0xffffffffu, p1, j);
            o0 = fmaf(pb, Vs[j + 32][l],      o0);
            o1 = fmaf(pb, Vs[j + 32][l + 32], o1);
        }
    }

#pragma unroll
    for (int off = 16; off; off >>= 1)
        ssum += __shfl_xor_sync(0xffffffffu, ssum, off);
    const float inv = 1.f / ssum;

    O[(size_t)i * D_MODEL + h * HEAD_DIM + l]      = o0 * inv;
    O[(size_t)i * D_MODEL + h * HEAD_DIM + 32 + l] = o1 * inv;
}

// ---------------------------------------------------------------------------
// Launch
// ---------------------------------------------------------------------------
extern "C" void kernel_launch(void* const* d_in, const int* in_sizes, int n_in,
                              void* d_out, int out_size)
{
    const float* X  = (const float*)d_in[0];
    const float* Wq = (const float*)d_in[1];
    const float* Wk = (const float*)d_in[2];
    const float* Wv = (const float*)d_in[3];
    const float* Wo = (const float*)d_in[4];
    float* out = (float*)d_out;

    float*  Qb;   cudaGetSymbolAddress((void**)&Qb,   g_Q);
    float*  Kb;   cudaGetSymbolAddress((void**)&Kb,   g_K);
    float*  Vb;   cudaGetSymbolAddress((void**)&Vb,   g_V);
    float*  Ob;   cudaGetSymbolAddress((void**)&Ob,   g_O);
    float2* X2;   cudaGetSymbolAddress((void**)&X2,   g_X2);
    float2* W2;   cudaGetSymbolAddress((void**)&W2,   g_Wqkv2);
    float2* Wo2;  cudaGetSymbolAddress((void**)&Wo2,  g_Wo2);
    float2* O2;   cudaGetSymbolAddress((void**)&O2,   g_O2);

    static bool attr_set = false;
    if (!attr_set) {
        cudaFuncSetAttribute(gemm_split, cudaFuncAttributeMaxDynamicSharedMemorySize, GEMM_SMEM);
        attr_set = true;
    }

    const int SB = 256;
    // pre-split inputs to tf32 hi/lo planes
    split2<<<(T_SEQ * D_MODEL / 4 + SB - 1) / SB, SB>>>(X,  X2,  T_SEQ * D_MODEL / 4);
    split2<<<(D_MODEL * D_MODEL / 4 + SB - 1) / SB, SB>>>(Wq, W2, D_MODEL * D_MODEL / 4);
    split2<<<(KV_DIM * D_MODEL / 4 + SB - 1) / SB, SB>>>(Wk, W2 + (size_t)D_MODEL * D_MODEL, KV_DIM * D_MODEL / 4);
    split2<<<(KV_DIM * D_MODEL / 4 + SB - 1) / SB, SB>>>(Wv, W2 + (size_t)(D_MODEL + KV_DIM) * D_MODEL, KV_DIM * D_MODEL / 4);
    split2<<<(D_MODEL * D_MODEL / 4 + SB - 1) / SB, SB>>>(Wo, Wo2, D_MODEL * D_MODEL / 4);

    rope_tables<<<(T_SEQ * 32 + 255) / 256, 256>>>();

    // fused QKV projection: [2048,3072] = X[2048,2048] @ Wqkv^T
    gemm_split<<<dim3(QKV_N / BN, T_SEQ / BM), 256, GEMM_SMEM>>>(
        X2, W2, T_SEQ, QKV_N, D_MODEL,
        Qb, D_MODEL, D_MODEL,
        Kb, D_MODEL + KV_DIM, KV_DIM,
        Vb, KV_DIM);

    rope_apply<<<(T_SEQ * N_HEADS * 32 + 255) / 256, 256>>>(Qb, N_HEADS);
    rope_apply<<<(T_SEQ * N_KV    * 32 + 255) / 256, 256>>>(Kb, N_KV);

    attn_kernel<<<dim3(T_SEQ / TQ, N_HEADS), TQ * 32>>>(Qb, Kb, Vb, Ob);

    // output projection
    split2<<<(T_SEQ * D_MODEL / 4 + SB - 1) / SB, SB>>>(Ob, O2, T_SEQ * D_MODEL / 4);
    gemm_split<<<dim3(D_MODEL / BN, T_SEQ / BM), 256, GEMM_SMEM>>>(
        O2, Wo2, T_SEQ, D_MODEL, D_MODEL,
        out, D_MODEL, D_MODEL,
        out, D_MODEL + 1, D_MODEL,
        out, D_MODEL);
}

// round 4
// speedup vs baseline: 1.9394x; 1.5947x over previous
#include <cuda_runtime.h>
#include <cuda_bf16.h>
#include <math.h>

// ---------------------------------------------------------------------------
// Problem constants
// ---------------------------------------------------------------------------
#define T_SEQ    2048
#define D_MODEL  2048
#define N_HEADS  32
#define N_KV     8
#define HEAD_DIM 64
#define KV_DIM   (N_KV * HEAD_DIM)       // 512
#define QKV_N    (D_MODEL + 2 * KV_DIM)  // 3072
#define WINDOW_HALF 256

// ---------------------------------------------------------------------------
// Scratch (device globals; no allocation allowed)
// ---------------------------------------------------------------------------
__device__ float  g_Q[(size_t)T_SEQ * D_MODEL];      // 16 MB
__device__ float  g_K[(size_t)T_SEQ * KV_DIM];       // 4 MB
__device__ float  g_V[(size_t)T_SEQ * KV_DIM];       // 4 MB
__device__ float  g_O[(size_t)T_SEQ * D_MODEL];      // 16 MB
__device__ float2 g_X2[(size_t)T_SEQ * D_MODEL];     // 32 MB  (hi,lo tf32 planes)
__device__ float2 g_Wqkv2[(size_t)QKV_N * D_MODEL];  // 48 MB
__device__ float2 g_Wo2[(size_t)D_MODEL * D_MODEL];  // 32 MB
__device__ float2 g_O2[(size_t)T_SEQ * D_MODEL];     // 32 MB
__device__ float  g_cos[T_SEQ * 32];
__device__ float  g_sin[T_SEQ * 32];

// ---------------------------------------------------------------------------
// tf32 helpers
// ---------------------------------------------------------------------------
__device__ __forceinline__ unsigned cvt_tf32(float x)
{
    unsigned r;
    asm("cvt.rna.tf32.f32 %0, %1;" : "=r"(r) : "f"(x));
    return r;
}
__device__ __forceinline__ float tf32f(float x) { return __uint_as_float(cvt_tf32(x)); }

__device__ __forceinline__ void mma_tf32(float* c, const unsigned* a, const unsigned* b)
{
    asm volatile(
        "mma.sync.aligned.m16n8k8.row.col.f32.tf32.tf32.f32 "
        "{%0,%1,%2,%3}, {%4,%5,%6,%7}, {%8,%9}, {%0,%1,%2,%3};"
        : "+f"(c[0]), "+f"(c[1]), "+f"(c[2]), "+f"(c[3])
        : "r"(a[0]), "r"(a[1]), "r"(a[2]), "r"(a[3]),
          "r"(b[0]), "r"(b[1]));
}

// ---------------------------------------------------------------------------
// Split fp32 -> interleaved (hi, lo) tf32 planes. n4 = count/4.
// ---------------------------------------------------------------------------
__global__ void split2(const float* __restrict__ s, float2* __restrict__ d, int n4)
{
    int i = blockIdx.x * blockDim.x + threadIdx.x;
    if (i >= n4) return;
    float4 v = ((const float4*)s)[i];
    float x[4] = {v.x, v.y, v.z, v.w};
    float2 o[4];
#pragma unroll
    for (int j = 0; j < 4; j++) {
        float hf = tf32f(x[j]);
        float lf = tf32f(x[j] - hf);
        o[j] = make_float2(hf, lf);
    }
    float4* dd = (float4*)(d + (size_t)i * 4);
    dd[0] = make_float4(o[0].x, o[0].y, o[1].x, o[1].y);
    dd[1] = make_float4(o[2].x, o[2].y, o[3].x, o[3].y);
}

// ---------------------------------------------------------------------------
// Pipelined tensor-core GEMM on pre-split operands (unchanged from round 3)
// ---------------------------------------------------------------------------
#define BM 128
#define BN 128
#define BK 16
#define SPAD2 18
#define TILE_F2 (128 * SPAD2)
#define STG_BYTES (TILE_F2 * 8)
#define GEMM_SMEM (4 * STG_BYTES)

__device__ __forceinline__ void cp16(unsigned dst, const void* src)
{
    asm volatile("cp.async.ca.shared.global [%0], [%1], 16;" :: "r"(dst), "l"(src));
}

__device__ __forceinline__ void stage_tiles(unsigned sA, unsigned sB,
                                            const float2* A2, const float2* B2,
                                            int K, int bm, int bn, int k0, int tid)
{
#pragma unroll
    for (int t = 0; t < 4; t++) {
        int id  = tid + t * 256;
        int row = id >> 3;
        int cp  = (id & 7) * 2;
        unsigned soff = (unsigned)(row * SPAD2 + cp) * 8u;
        cp16(sA + soff, A2 + (size_t)(bm + row) * K + k0 + cp);
        cp16(sB + soff, B2 + (size_t)(bn + row) * K + k0 + cp);
    }
}

__global__ void __launch_bounds__(256)
gemm_split(const float2* __restrict__ A2, const float2* __restrict__ B2,
           int M, int N, int K,
           float* __restrict__ C0, int n0, int s0,
           float* __restrict__ C1, int n1, int s1,
           float* __restrict__ C2, int s2)
{
    extern __shared__ float2 sm[];
    float2* As = sm;
    float2* Bs = sm + 2 * TILE_F2;
    unsigned sAu = (unsigned)__cvta_generic_to_shared(As);
    unsigned sBu = (unsigned)__cvta_generic_to_shared(Bs);

    const int tid = threadIdx.x;
    const int bm = blockIdx.y * BM;
    const int bn = blockIdx.x * BN;

    const int warp = tid >> 5;
    const int lane = tid & 31;
    const int qr = lane >> 2;
    const int qc = lane & 3;
    const int wr = warp >> 2;
    const int wc = warp & 3;

    float acc[4][4][4];
#pragma unroll
    for (int i = 0; i < 4; i++)
#pragma unroll
        for (int j = 0; j < 4; j++)
#pragma unroll
            for (int r = 0; r < 4; r++) acc[i][j][r] = 0.f;

    const int NS = K / BK;

    stage_tiles(sAu, sBu, A2, B2, K, bm, bn, 0, tid);
    asm volatile("cp.async.commit_group;" ::: "memory");
    stage_tiles(sAu + STG_BYTES, sBu + STG_BYTES, A2, B2, K, bm, bn, BK, tid);
    asm volatile("cp.async.commit_group;" ::: "memory");

    for (int s = 0; s < NS; s++) {
        asm volatile("cp.async.wait_group 1;" ::: "memory");
        __syncthreads();

        const int buf = s & 1;
        const float2* At = As + buf * TILE_F2;
        const float2* Bt = Bs + buf * TILE_F2;

#pragma unroll
        for (int ks = 0; ks < BK; ks += 8) {
            float2 a[4][4], b[4][2];
#pragma unroll
            for (int mt = 0; mt < 4; mt++) {
                const int r = wr * 64 + mt * 16 + qr;
                a[mt][0] = At[r * SPAD2 + ks + qc];
                a[mt][1] = At[(r + 8) * SPAD2 + ks + qc];
                a[mt][2] = At[r * SPAD2 + ks + qc + 4];
                a[mt][3] = At[(r + 8) * SPAD2 + ks + qc + 4];
            }
#pragma unroll
            for (int nt = 0; nt < 4; nt++) {
                const int n = wc * 32 + nt * 8 + qr;
                b[nt][0] = Bt[n * SPAD2 + ks + qc];
                b[nt][1] = Bt[n * SPAD2 + ks + qc + 4];
            }
#pragma unroll
            for (int mt = 0; mt < 4; mt++) {
                unsigned ah[4], al[4];
#pragma unroll
                for (int r = 0; r < 4; r++) {
                    ah[r] = __float_as_uint(a[mt][r].x);
                    al[r] = __float_as_uint(a[mt][r].y);
                }
#pragma unroll
                for (int nt = 0; nt < 4; nt++) {
                    unsigned bh[2] = {__float_as_uint(b[nt][0].x), __float_as_uint(b[nt][1].x)};
                    unsigned bl[2] = {__float_as_uint(b[nt][0].y), __float_as_uint(b[nt][1].y)};
                    mma_tf32(acc[mt][nt], ah, bh);
                    mma_tf32(acc[mt][nt], ah, bl);
                    mma_tf32(acc[mt][nt], al, bh);
                }
            }
        }
        __syncthreads();

        if (s + 2 < NS)
            stage_tiles(sAu + buf * STG_BYTES, sBu + buf * STG_BYTES,
                        A2, B2, K, bm, bn, (s + 2) * BK, tid);
        asm volatile("cp.async.commit_group;" ::: "memory");
    }

    float* C; int col0, stride;
    if (bn < n0)      { C = C0; col0 = bn;      stride = s0; }
    else if (bn < n1) { C = C1; col0 = bn - n0; stride = s1; }
    else              { C = C2; col0 = bn - n1; stride = s2; }

#pragma unroll
    for (int mt = 0; mt < 4; mt++) {
        const int row0 = bm + wr * 64 + mt * 16 + qr;
#pragma unroll
        for (int nt = 0; nt < 4; nt++) {
            const int col = col0 + wc * 32 + nt * 8 + qc * 2;
            *(float2*)(C + (size_t)row0       * stride + col) = make_float2(acc[mt][nt][0], acc[mt][nt][1]);
            *(float2*)(C + (size_t)(row0 + 8) * stride + col) = make_float2(acc[mt][nt][2], acc[mt][nt][3]);
        }
    }
}

// ---------------------------------------------------------------------------
// RoPE
// ---------------------------------------------------------------------------
__global__ void rope_tables()
{
    int idx = blockIdx.x * blockDim.x + threadIdx.x;
    if (idx >= T_SEQ * 32) return;
    int i = idx & 31;
    int t = idx >> 5;
    double invf = exp2(-(double)i / 32.0 * 13.287712379549449392);
    double ang  = fmod((double)t * invf, 6.28318530717958647692);
    g_cos[idx] = cosf((float)ang);
    g_sin[idx] = sinf((float)ang);
}

__global__ void rope_apply(float* __restrict__ X, int nheads)
{
    int idx = blockIdx.x * blockDim.x + threadIdx.x;
    int total = T_SEQ * nheads * 32;
    if (idx >= total) return;
    int i = idx & 31;
    int h = (idx >> 5) % nheads;
    int t = idx / (32 * nheads);
    float c = g_cos[t * 32 + i];
    float s = g_sin[t * 32 + i];
    float* row = X + (size_t)t * (nheads * HEAD_DIM) + h * HEAD_DIM;
    float x0 = row[i];
    float x1 = row[i + 32];
    row[i]      = x0 * c - x1 * s;
    row[i + 32] = x1 * c + x0 * s;
}

// ---------------------------------------------------------------------------
// Tensor-core banded GQA attention.
// Block = 64-query tile x 1 head, 128 threads (4 warps, 16 q-rows each).
// Streams 64-key chunks; S and O via mma.m16n8k8.tf32; softmax without max
// subtraction (scores bounded). P round-trips through warp-private smem.
// ---------------------------------------------------------------------------
#define QT   64
#define CHK  64
#define APAD 68
#define ATTN_SMEM (3 * QT * APAD * 4)   // Qs/Ps, Ks, Vs = 52224 B

__global__ void __launch_bounds__(128)
attn_mma(const float* __restrict__ Q, const float* __restrict__ K,
         const float* __restrict__ V, float* __restrict__ O)
{
    extern __shared__ float asm_[];
    float* Qs = asm_;                    // [QT][APAD]; reused as Ps
    float* Ks = asm_ + QT * APAD;        // [CHK][APAD]  ([j][d])
    float* Vs = asm_ + 2 * QT * APAD;    // [CHK][APAD]  ([j][d])

    const int h  = blockIdx.y;
    const int g  = h >> 2;
    const int q0 = blockIdx.x * QT;
    const int tid = threadIdx.x;
    const int w = tid >> 5;
    const int lane = tid & 31;
    const int qr = lane >> 2;
    const int qc = lane & 3;

    // stage Q tile (rows q0.., head h) as tf32
#pragma unroll
    for (int t = 0; t < 8; t++) {
        int idx = tid + t * 128;          // 1024 float4 slots
        int r  = idx >> 4;
        int d4 = (idx & 15) * 4;
        float4 v = *(const float4*)(Q + (size_t)(q0 + r) * D_MODEL + h * HEAD_DIM + d4);
        Qs[r * APAD + d4 + 0] = tf32f(v.x);
        Qs[r * APAD + d4 + 1] = tf32f(v.y);
        Qs[r * APAD + d4 + 2] = tf32f(v.z);
        Qs[r * APAD + d4 + 3] = tf32f(v.w);
    }
    __syncthreads();

    // hoist Q A-fragments (warp-private rows) for all 8 k-steps
    unsigned qa[8][4];
    {
        const int m0 = w * 16 + qr;
#pragma unroll
        for (int ks = 0; ks < 8; ks++) {
            qa[ks][0] = __float_as_uint(Qs[m0 * APAD + ks * 8 + qc]);
            qa[ks][1] = __float_as_uint(Qs[(m0 + 8) * APAD + ks * 8 + qc]);
            qa[ks][2] = __float_as_uint(Qs[m0 * APAD + ks * 8 + qc + 4]);
            qa[ks][3] = __float_as_uint(Qs[(m0 + 8) * APAD + ks * 8 + qc + 4]);
        }
    }
    // Qs rows [w*16, w*16+16) now warp-private -> reuse as Ps
    float* Ps = Qs;

    float oacc[8][4];
#pragma unroll
    for (int nt = 0; nt < 8; nt++)
#pragma unroll
        for (int r = 0; r < 4; r++) oacc[nt][r] = 0.f;
    float rs0 = 0.f, rs1 = 0.f;

    const int i0 = q0 + w * 16 + qr;     // row index of c0/c1 regs
    const int i1 = i0 + 8;               // row index of c2/c3 regs
    const float SC = 0.125f * 1.44269504088896f;   // (1/sqrt(64)) * log2(e)

    const int jstart = max(0, q0 - WINDOW_HALF);
    const int jend   = min(T_SEQ, q0 + QT + WINDOW_HALF);   // multiples of 64

    for (int c = jstart; c < jend; c += CHK) {
        __syncthreads();
        // stage K, V chunks as tf32 (no bounds needed: chunk fully in range)
#pragma unroll
        for (int t = 0; t < 8; t++) {
            int idx = tid + t * 128;
            int r  = idx >> 4;
            int d4 = (idx & 15) * 4;
            const size_t go = (size_t)(c + r) * KV_DIM + g * HEAD_DIM + d4;
            float4 kv = *(const float4*)(K + go);
            float4 vv = *(const float4*)(V + go);
            Ks[r * APAD + d4 + 0] = tf32f(kv.x);
            Ks[r * APAD + d4 + 1] = tf32f(kv.y);
            Ks[r * APAD + d4 + 2] = tf32f(kv.z);
            Ks[r * APAD + d4 + 3] = tf32f(kv.w);
            Vs[r * APAD + d4 + 0] = tf32f(vv.x);
            Vs[r * APAD + d4 + 1] = tf32f(vv.y);
            Vs[r * APAD + d4 + 2] = tf32f(vv.z);
            Vs[r * APAD + d4 + 3] = tf32f(vv.w);
        }
        __syncthreads();

        // S = Q K^T  (warp rows x 64 keys)
        float sfr[8][4];
#pragma unroll
        for (int nt = 0; nt < 8; nt++) {
#pragma unroll
            for (int r = 0; r < 4; r++) sfr[nt][r] = 0.f;
        }
#pragma unroll
        for (int ks = 0; ks < 8; ks++) {
#pragma unroll
            for (int nt = 0; nt < 8; nt++) {
                const int n = nt * 8 + qr;
                unsigned b[2] = {
                    __float_as_uint(Ks[n * APAD + ks * 8 + qc]),
                    __float_as_uint(Ks[n * APAD + ks * 8 + qc + 4])
                };
                mma_tf32(sfr[nt], qa[ks], b);
            }
        }

        // mask + exp + rowsum + store P (tf32) to warp-private smem
        const int m0 = w * 16 + qr;
#pragma unroll
        for (int nt = 0; nt < 8; nt++) {
            const int j0 = c + nt * 8 + 2 * qc;
            const int j1 = j0 + 1;
            float p00 = (j0 >= i0 - WINDOW_HALF && j0 < i0 + WINDOW_HALF) ? exp2f(sfr[nt][0] * SC) : 0.f;
            float p01 = (j1 >= i0 - WINDOW_HALF && j1 < i0 + WINDOW_HALF) ? exp2f(sfr[nt][1] * SC) : 0.f;
            float p10 = (j0 >= i1 - WINDOW_HALF && j0 < i1 + WINDOW_HALF) ? exp2f(sfr[nt][2] * SC) : 0.f;
            float p11 = (j1 >= i1 - WINDOW_HALF && j1 < i1 + WINDOW_HALF) ? exp2f(sfr[nt][3] * SC) : 0.f;
            rs0 += p00 + p01;
            rs1 += p10 + p11;
            *(float2*)&Ps[m0 * APAD + nt * 8 + 2 * qc]       = make_float2(tf32f(p00), tf32f(p01));
            *(float2*)&Ps[(m0 + 8) * APAD + nt * 8 + 2 * qc] = make_float2(tf32f(p10), tf32f(p11));
        }
        __syncwarp();

        // O += P V
#pragma unroll
        for (int ks = 0; ks < 8; ks++) {
            unsigned a[4] = {
                __float_as_uint(Ps[m0 * APAD + ks * 8 + qc]),
                __float_as_uint(Ps[(m0 + 8) * APAD + ks * 8 + qc]),
                __float_as_uint(Ps[m0 * APAD + ks * 8 + qc + 4]),
                __float_as_uint(Ps[(m0 + 8) * APAD + ks * 8 + qc + 4])
            };
#pragma unroll
            for (int nt = 0; nt < 8; nt++) {
                const int n = nt * 8 + qr;   // d index
                unsigned b[2] = {
                    __float_as_uint(Vs[(ks * 8 + qc) * APAD + n]),
                    __float_as_uint(Vs[(ks * 8 + qc + 4) * APAD + n])
                };
                mma_tf32(oacc[nt], a, b);
            }
        }
        __syncwarp();   // Ps reused next chunk
    }

    // finalize row sums (cols were partitioned over the 4 qc lanes)
    rs0 += __shfl_xor_sync(0xffffffffu, rs0, 1);
    rs0 += __shfl_xor_sync(0xffffffffu, rs0, 2);
    rs1 += __shfl_xor_sync(0xffffffffu, rs1, 1);
    rs1 += __shfl_xor_sync(0xffffffffu, rs1, 2);
    const float inv0 = 1.f / rs0;
    const float inv1 = 1.f / rs1;

#pragma unroll
    for (int nt = 0; nt < 8; nt++) {
        const int col = h * HEAD_DIM + nt * 8 + 2 * qc;
        *(float2*)(O + (size_t)i0 * D_MODEL + col) = make_float2(oacc[nt][0] * inv0, oacc[nt][1] * inv0);
        *(float2*)(O + (size_t)i1 * D_MODEL + col) = make_float2(oacc[nt][2] * inv1, oacc[nt][3] * inv1);
    }
}

// ---------------------------------------------------------------------------
// Launch
// ---------------------------------------------------------------------------
extern "C" void kernel_launch(void* const* d_in, const int* in_sizes, int n_in,
                              void* d_out, int out_size)
{
    const float* X  = (const float*)d_in[0];
    const float* Wq = (const float*)d_in[1];
    const float* Wk = (const float*)d_in[2];
    const float* Wv = (const float*)d_in[3];
    const float* Wo = (const float*)d_in[4];
    float* out = (float*)d_out;

    float*  Qb;   cudaGetSymbolAddress((void**)&Qb,   g_Q);
    float*  Kb;   cudaGetSymbolAddress((void**)&Kb,   g_K);
    float*  Vb;   cudaGetSymbolAddress((void**)&Vb,   g_V);
    float*  Ob;   cudaGetSymbolAddress((void**)&Ob,   g_O);
    float2* X2;   cudaGetSymbolAddress((void**)&X2,   g_X2);
    float2* W2;   cudaGetSymbolAddress((void**)&W2,   g_Wqkv2);
    float2* Wo2;  cudaGetSymbolAddress((void**)&Wo2,  g_Wo2);
    float2* O2;   cudaGetSymbolAddress((void**)&O2,   g_O2);

    static bool attr_set = false;
    if (!attr_set) {
        cudaFuncSetAttribute(gemm_split, cudaFuncAttributeMaxDynamicSharedMemorySize, GEMM_SMEM);
        cudaFuncSetAttribute(attn_mma,  cudaFuncAttributeMaxDynamicSharedMemorySize, ATTN_SMEM);
        attr_set = true;
    }

    const int SB = 256;
    split2<<<(T_SEQ * D_MODEL / 4 + SB - 1) / SB, SB>>>(X,  X2,  T_SEQ * D_MODEL / 4);
    split2<<<(D_MODEL * D_MODEL / 4 + SB - 1) / SB, SB>>>(Wq, W2, D_MODEL * D_MODEL / 4);
    split2<<<(KV_DIM * D_MODEL / 4 + SB - 1) / SB, SB>>>(Wk, W2 + (size_t)D_MODEL * D_MODEL, KV_DIM * D_MODEL / 4);
    split2<<<(KV_DIM * D_MODEL / 4 + SB - 1) / SB, SB>>>(Wv, W2 + (size_t)(D_MODEL + KV_DIM) * D_MODEL, KV_DIM * D_MODEL / 4);
    split2<<<(D_MODEL * D_MODEL / 4 + SB - 1) / SB, SB>>>(Wo, Wo2, D_MODEL * D_MODEL / 4);

    rope_tables<<<(T_SEQ * 32 + 255) / 256, 256>>>();

    gemm_split<<<dim3(QKV_N / BN, T_SEQ / BM), 256, GEMM_SMEM>>>(
        X2, W2, T_SEQ, QKV_N, D_MODEL,
        Qb, D_MODEL, D_MODEL,
        Kb, D_MODEL + KV_DIM, KV_DIM,
        Vb, KV_DIM);

    rope_apply<<<(T_SEQ * N_HEADS * 32 + 255) / 256, 256>>>(Qb, N_HEADS);
    rope_apply<<<(T_SEQ * N_KV    * 32 + 255) / 256, 256>>>(Kb, N_KV);

    attn_mma<<<dim3(T_SEQ / QT, N_HEADS), 128, ATTN_SMEM>>>(Qb, Kb, Vb, Ob);

    split2<<<(T_SEQ * D_MODEL / 4 + SB - 1) / SB, SB>>>(Ob, O2, T_SEQ * D_MODEL / 4);
    gemm_split<<<dim3(D_MODEL / BN, T_SEQ / BM), 256, GEMM_SMEM>>>(
        O2, Wo2, T_SEQ, D_MODEL, D_MODEL,
        out, D_MODEL, D_MODEL,
        out, D_MODEL + 1, D_MODEL,
        out, D_MODEL);
}

// round 5
// speedup vs baseline: 3.7274x; 1.9219x over previous
#include <cuda_runtime.h>
#include <cuda_bf16.h>
#include <math.h>

// ---------------------------------------------------------------------------
// Problem constants
// ---------------------------------------------------------------------------
#define T_SEQ    2048
#define D_MODEL  2048
#define N_HEADS  32
#define N_KV     8
#define HEAD_DIM 64
#define KV_DIM   (N_KV * HEAD_DIM)       // 512
#define QKV_N    (D_MODEL + 2 * KV_DIM)  // 3072
#define WINDOW_HALF 256

// ---------------------------------------------------------------------------
// Scratch (device globals; no allocation allowed)
// ---------------------------------------------------------------------------
__device__ float g_Q[(size_t)T_SEQ * D_MODEL];     // 16 MB
__device__ float g_K[(size_t)T_SEQ * KV_DIM];      // 4 MB
__device__ float g_V[(size_t)T_SEQ * KV_DIM];      // 4 MB
__device__ __nv_bfloat16 g_Xh[(size_t)T_SEQ * D_MODEL];
__device__ __nv_bfloat16 g_Xl[(size_t)T_SEQ * D_MODEL];
__device__ __nv_bfloat16 g_Wh[(size_t)QKV_N * D_MODEL];
__device__ __nv_bfloat16 g_Wl[(size_t)QKV_N * D_MODEL];
__device__ __nv_bfloat16 g_Woh[(size_t)D_MODEL * D_MODEL];
__device__ __nv_bfloat16 g_Wol[(size_t)D_MODEL * D_MODEL];
__device__ __nv_bfloat16 g_Oh[(size_t)T_SEQ * D_MODEL];
__device__ __nv_bfloat16 g_Ol[(size_t)T_SEQ * D_MODEL];
__device__ float g_cos[T_SEQ * 32];
__device__ float g_sin[T_SEQ * 32];

// ---------------------------------------------------------------------------
// helpers
// ---------------------------------------------------------------------------
__device__ __forceinline__ unsigned cvt_tf32(float x)
{
    unsigned r;
    asm("cvt.rna.tf32.f32 %0, %1;" : "=r"(r) : "f"(x));
    return r;
}
__device__ __forceinline__ float tf32f(float x) { return __uint_as_float(cvt_tf32(x)); }

__device__ __forceinline__ void mma_tf32(float* c, const unsigned* a, const unsigned* b)
{
    asm volatile(
        "mma.sync.aligned.m16n8k8.row.col.f32.tf32.tf32.f32 "
        "{%0,%1,%2,%3}, {%4,%5,%6,%7}, {%8,%9}, {%0,%1,%2,%3};"
        : "+f"(c[0]), "+f"(c[1]), "+f"(c[2]), "+f"(c[3])
        : "r"(a[0]), "r"(a[1]), "r"(a[2]), "r"(a[3]),
          "r"(b[0]), "r"(b[1]));
}

__device__ __forceinline__ void mma_bf16(float* c, const unsigned* a, const unsigned* b)
{
    asm volatile(
        "mma.sync.aligned.m16n8k16.row.col.f32.bf16.bf16.f32 "
        "{%0,%1,%2,%3}, {%4,%5,%6,%7}, {%8,%9}, {%0,%1,%2,%3};"
        : "+f"(c[0]), "+f"(c[1]), "+f"(c[2]), "+f"(c[3])
        : "r"(a[0]), "r"(a[1]), "r"(a[2]), "r"(a[3]),
          "r"(b[0]), "r"(b[1]));
}

// ---------------------------------------------------------------------------
// Split fp32 -> bf16 hi/lo planes. n4 = count/4.
// ---------------------------------------------------------------------------
__global__ void split_bf(const float* __restrict__ s,
                         __nv_bfloat16* __restrict__ hi,
                         __nv_bfloat16* __restrict__ lo, int n4)
{
    int i = blockIdx.x * blockDim.x + threadIdx.x;
    if (i >= n4) return;
    float4 v = ((const float4*)s)[i];
    float x[4] = {v.x, v.y, v.z, v.w};
    __nv_bfloat16 h[4], l[4];
#pragma unroll
    for (int j = 0; j < 4; j++) {
        h[j] = __float2bfloat16(x[j]);
        l[j] = __float2bfloat16(x[j] - __bfloat162float(h[j]));
    }
    __nv_bfloat162* hp = (__nv_bfloat162*)hi;
    __nv_bfloat162* lp = (__nv_bfloat162*)lo;
    hp[2 * i]     = __nv_bfloat162(h[0], h[1]);
    hp[2 * i + 1] = __nv_bfloat162(h[2], h[3]);
    lp[2 * i]     = __nv_bfloat162(l[0], l[1]);
    lp[2 * i + 1] = __nv_bfloat162(l[2], l[3]);
}

// ---------------------------------------------------------------------------
// bf16x3-split tensor-core GEMM:  C[M,N] = A[M,K] * B[N,K]^T
// Block 128x128x32, 256 threads (8 warps, warp tile 64x32), 2-stage cp.async.
// Planes (hi/lo) stored separately in smem; rows padded to 40 bf16 (80 B)
// -> conflict-free 32-bit fragment loads.
// ---------------------------------------------------------------------------
#define BM 128
#define BN 128
#define GBK 32
#define KPAD 40
#define PLANE_E (128 * KPAD)             // bf16 elems per plane tile
#define STAGE_E (4 * PLANE_E)            // Ah, Al, Bh, Bl
#define STAGE_B (STAGE_E * 2)            // 40960 bytes
#define GEMM_SMEM (2 * STAGE_B)          // 81920 bytes

__device__ __forceinline__ void cp16(unsigned dst, const void* src)
{
    asm volatile("cp.async.ca.shared.global [%0], [%1], 16;" :: "r"(dst), "l"(src));
}

__device__ __forceinline__ void stage_bf(unsigned sbase,
                                         const __nv_bfloat16* Ah, const __nv_bfloat16* Al,
                                         const __nv_bfloat16* Bh, const __nv_bfloat16* Bl,
                                         int K, int bm, int bn, int k0, int tid)
{
#pragma unroll
    for (int t = 0; t < 8; t++) {
        int id = tid + t * 256;              // 0..2047
        int plane = id >> 9;                 // 0..3
        int r = (id >> 2) & 127;
        int c = id & 3;                      // 16B chunk (8 bf16)
        unsigned dst = sbase + (unsigned)(plane * PLANE_E + r * KPAD + c * 8) * 2u;
        const __nv_bfloat16* src;
        if (plane == 0)      src = Ah + (size_t)(bm + r) * K + k0 + c * 8;
        else if (plane == 1) src = Al + (size_t)(bm + r) * K + k0 + c * 8;
        else if (plane == 2) src = Bh + (size_t)(bn + r) * K + k0 + c * 8;
        else                 src = Bl + (size_t)(bn + r) * K + k0 + c * 8;
        cp16(dst, src);
    }
}

__global__ void __launch_bounds__(256, 2)
gemm_bf3(const __nv_bfloat16* __restrict__ Ah, const __nv_bfloat16* __restrict__ Al,
         const __nv_bfloat16* __restrict__ Bh, const __nv_bfloat16* __restrict__ Bl,
         int K,
         float* __restrict__ C0, int n0, int s0,
         float* __restrict__ C1, int n1, int s1,
         float* __restrict__ C2, int s2)
{
    extern __shared__ __nv_bfloat16 smb[];
    unsigned sbase = (unsigned)__cvta_generic_to_shared(smb);

    const int tid = threadIdx.x;
    const int bm = blockIdx.y * BM;
    const int bn = blockIdx.x * BN;

    const int warp = tid >> 5;
    const int lane = tid & 31;
    const int qr = lane >> 2;
    const int qc = lane & 3;
    const int wr = warp >> 2;       // 0..1
    const int wc = warp & 3;        // 0..3

    float acc[4][4][4];
#pragma unroll
    for (int i = 0; i < 4; i++)
#pragma unroll
        for (int j = 0; j < 4; j++)
#pragma unroll
            for (int r = 0; r < 4; r++) acc[i][j][r] = 0.f;

    const int NS = K / GBK;

    stage_bf(sbase, Ah, Al, Bh, Bl, K, bm, bn, 0, tid);
    asm volatile("cp.async.commit_group;" ::: "memory");
    stage_bf(sbase + STAGE_B, Ah, Al, Bh, Bl, K, bm, bn, GBK, tid);
    asm volatile("cp.async.commit_group;" ::: "memory");

    for (int s = 0; s < NS; s++) {
        asm volatile("cp.async.wait_group 1;" ::: "memory");
        __syncthreads();

        const int buf = s & 1;
        const __nv_bfloat16* Ath = smb + buf * STAGE_E;
        const __nv_bfloat16* Atl = Ath + PLANE_E;
        const __nv_bfloat16* Bth = Ath + 2 * PLANE_E;
        const __nv_bfloat16* Btl = Ath + 3 * PLANE_E;

#pragma unroll
        for (int ks = 0; ks < GBK; ks += 16) {
            unsigned ah[4][4], al[4][4];
#pragma unroll
            for (int mt = 0; mt < 4; mt++) {
                const int r0 = wr * 64 + mt * 16 + qr;
                const int o00 = r0 * KPAD + ks + 2 * qc;
                const int o10 = (r0 + 8) * KPAD + ks + 2 * qc;
                ah[mt][0] = *(const unsigned*)&Ath[o00];
                ah[mt][1] = *(const unsigned*)&Ath[o10];
                ah[mt][2] = *(const unsigned*)&Ath[o00 + 8];
                ah[mt][3] = *(const unsigned*)&Ath[o10 + 8];
                al[mt][0] = *(const unsigned*)&Atl[o00];
                al[mt][1] = *(const unsigned*)&Atl[o10];
                al[mt][2] = *(const unsigned*)&Atl[o00 + 8];
                al[mt][3] = *(const unsigned*)&Atl[o10 + 8];
            }
#pragma unroll
            for (int nt = 0; nt < 4; nt++) {
                const int n0r = wc * 32 + nt * 8 + qr;
                const int ob = n0r * KPAD + ks + 2 * qc;
                unsigned bh[2] = {*(const unsigned*)&Bth[ob], *(const unsigned*)&Bth[ob + 8]};
                unsigned bl[2] = {*(const unsigned*)&Btl[ob], *(const unsigned*)&Btl[ob + 8]};
#pragma unroll
                for (int mt = 0; mt < 4; mt++) {
                    mma_bf16(acc[mt][nt], ah[mt], bh);
                    mma_bf16(acc[mt][nt], ah[mt], bl);
                    mma_bf16(acc[mt][nt], al[mt], bh);
                }
            }
        }
        __syncthreads();

        if (s + 2 < NS)
            stage_bf(sbase + buf * STAGE_B, Ah, Al, Bh, Bl, K, bm, bn, (s + 2) * GBK, tid);
        asm volatile("cp.async.commit_group;" ::: "memory");
    }

    float* C; int col0, stride;
    if (bn < n0)      { C = C0; col0 = bn;      stride = s0; }
    else if (bn < n1) { C = C1; col0 = bn - n0; stride = s1; }
    else              { C = C2; col0 = bn - n1; stride = s2; }

#pragma unroll
    for (int mt = 0; mt < 4; mt++) {
        const int row0 = bm + wr * 64 + mt * 16 + qr;
#pragma unroll
        for (int nt = 0; nt < 4; nt++) {
            const int col = col0 + wc * 32 + nt * 8 + qc * 2;
            *(float2*)(C + (size_t)row0       * stride + col) = make_float2(acc[mt][nt][0], acc[mt][nt][1]);
            *(float2*)(C + (size_t)(row0 + 8) * stride + col) = make_float2(acc[mt][nt][2], acc[mt][nt][3]);
        }
    }
}

// ---------------------------------------------------------------------------
// RoPE
// ---------------------------------------------------------------------------
__global__ void rope_tables()
{
    int idx = blockIdx.x * blockDim.x + threadIdx.x;
    if (idx >= T_SEQ * 32) return;
    int i = idx & 31;
    int t = idx >> 5;
    double invf = exp2(-(double)i / 32.0 * 13.287712379549449392);
    double ang  = fmod((double)t * invf, 6.28318530717958647692);
    g_cos[idx] = cosf((float)ang);
    g_sin[idx] = sinf((float)ang);
}

__global__ void rope_apply(float* __restrict__ X, int nheads)
{
    int idx = blockIdx.x * blockDim.x + threadIdx.x;
    int total = T_SEQ * nheads * 32;
    if (idx >= total) return;
    int i = idx & 31;
    int h = (idx >> 5) % nheads;
    int t = idx / (32 * nheads);
    float c = g_cos[t * 32 + i];
    float s = g_sin[t * 32 + i];
    float* row = X + (size_t)t * (nheads * HEAD_DIM) + h * HEAD_DIM;
    float x0 = row[i];
    float x1 = row[i + 32];
    row[i]      = x0 * c - x1 * s;
    row[i + 32] = x1 * c + x0 * s;
}

// ---------------------------------------------------------------------------
// Tensor-core banded GQA attention (round-4 kernel; epilogue now emits
// bf16 hi/lo planes for the output projection).
// ---------------------------------------------------------------------------
#define QT   64
#define CHK  64
#define APAD 68
#define ATTN_SMEM (3 * QT * APAD * 4)

__global__ void __launch_bounds__(128)
attn_mma(const float* __restrict__ Q, const float* __restrict__ K,
         const float* __restrict__ V,
         __nv_bfloat16* __restrict__ Oh, __nv_bfloat16* __restrict__ Ol)
{
    extern __shared__ float asm_[];
    float* Qs = asm_;
    float* Ks = asm_ + QT * APAD;
    float* Vs = asm_ + 2 * QT * APAD;

    const int h  = blockIdx.y;
    const int g  = h >> 2;
    const int q0 = blockIdx.x * QT;
    const int tid = threadIdx.x;
    const int w = tid >> 5;
    const int lane = tid & 31;
    const int qr = lane >> 2;
    const int qc = lane & 3;

#pragma unroll
    for (int t = 0; t < 8; t++) {
        int idx = tid + t * 128;
        int r  = idx >> 4;
        int d4 = (idx & 15) * 4;
        float4 v = *(const float4*)(Q + (size_t)(q0 + r) * D_MODEL + h * HEAD_DIM + d4);
        Qs[r * APAD + d4 + 0] = tf32f(v.x);
        Qs[r * APAD + d4 + 1] = tf32f(v.y);
        Qs[r * APAD + d4 + 2] = tf32f(v.z);
        Qs[r * APAD + d4 + 3] = tf32f(v.w);
    }
    __syncthreads();

    unsigned qa[8][4];
    {
        const int m0 = w * 16 + qr;
#pragma unroll
        for (int ks = 0; ks < 8; ks++) {
            qa[ks][0] = __float_as_uint(Qs[m0 * APAD + ks * 8 + qc]);
            qa[ks][1] = __float_as_uint(Qs[(m0 + 8) * APAD + ks * 8 + qc]);
            qa[ks][2] = __float_as_uint(Qs[m0 * APAD + ks * 8 + qc + 4]);
            qa[ks][3] = __float_as_uint(Qs[(m0 + 8) * APAD + ks * 8 + qc + 4]);
        }
    }
    float* Ps = Qs;

    float oacc[8][4];
#pragma unroll
    for (int nt = 0; nt < 8; nt++)
#pragma unroll
        for (int r = 0; r < 4; r++) oacc[nt][r] = 0.f;
    float rs0 = 0.f, rs1 = 0.f;

    const int i0 = q0 + w * 16 + qr;
    const int i1 = i0 + 8;
    const float SC = 0.125f * 1.44269504088896f;

    const int jstart = max(0, q0 - WINDOW_HALF);
    const int jend   = min(T_SEQ, q0 + QT + WINDOW_HALF);

    for (int c = jstart; c < jend; c += CHK) {
        __syncthreads();
#pragma unroll
        for (int t = 0; t < 8; t++) {
            int idx = tid + t * 128;
            int r  = idx >> 4;
            int d4 = (idx & 15) * 4;
            const size_t go = (size_t)(c + r) * KV_DIM + g * HEAD_DIM + d4;
            float4 kv = *(const float4*)(K + go);
            float4 vv = *(const float4*)(V + go);
            Ks[r * APAD + d4 + 0] = tf32f(kv.x);
            Ks[r * APAD + d4 + 1] = tf32f(kv.y);
            Ks[r * APAD + d4 + 2] = tf32f(kv.z);
            Ks[r * APAD + d4 + 3] = tf32f(kv.w);
            Vs[r * APAD + d4 + 0] = tf32f(vv.x);
            Vs[r * APAD + d4 + 1] = tf32f(vv.y);
            Vs[r * APAD + d4 + 2] = tf32f(vv.z);
            Vs[r * APAD + d4 + 3] = tf32f(vv.w);
        }
        __syncthreads();

        float sfr[8][4];
#pragma unroll
        for (int nt = 0; nt < 8; nt++)
#pragma unroll
            for (int r = 0; r < 4; r++) sfr[nt][r] = 0.f;
#pragma unroll
        for (int ks = 0; ks < 8; ks++) {
#pragma unroll
            for (int nt = 0; nt < 8; nt++) {
                const int n = nt * 8 + qr;
                unsigned b[2] = {
                    __float_as_uint(Ks[n * APAD + ks * 8 + qc]),
                    __float_as_uint(Ks[n * APAD + ks * 8 + qc + 4])
                };
                mma_tf32(sfr[nt], qa[ks], b);
            }
        }

        const int m0 = w * 16 + qr;
#pragma unroll
        for (int nt = 0; nt < 8; nt++) {
            const int j0 = c + nt * 8 + 2 * qc;
            const int j1 = j0 + 1;
            float p00 = (j0 >= i0 - WINDOW_HALF && j0 < i0 + WINDOW_HALF) ? exp2f(sfr[nt][0] * SC) : 0.f;
            float p01 = (j1 >= i0 - WINDOW_HALF && j1 < i0 + WINDOW_HALF) ? exp2f(sfr[nt][1] * SC) : 0.f;
            float p10 = (j0 >= i1 - WINDOW_HALF && j0 < i1 + WINDOW_HALF) ? exp2f(sfr[nt][2] * SC) : 0.f;
            float p11 = (j1 >= i1 - WINDOW_HALF && j1 < i1 + WINDOW_HALF) ? exp2f(sfr[nt][3] * SC) : 0.f;
            rs0 += p00 + p01;
            rs1 += p10 + p11;
            *(float2*)&Ps[m0 * APAD + nt * 8 + 2 * qc]       = make_float2(tf32f(p00), tf32f(p01));
            *(float2*)&Ps[(m0 + 8) * APAD + nt * 8 + 2 * qc] = make_float2(tf32f(p10), tf32f(p11));
        }
        __syncwarp();

#pragma unroll
        for (int ks = 0; ks < 8; ks++) {
            unsigned a[4] = {
                __float_as_uint(Ps[m0 * APAD + ks * 8 + qc]),
                __float_as_uint(Ps[(m0 + 8) * APAD + ks * 8 + qc]),
                __float_as_uint(Ps[m0 * APAD + ks * 8 + qc + 4]),
                __float_as_uint(Ps[(m0 + 8) * APAD + ks * 8 + qc + 4])
            };
#pragma unroll
            for (int nt = 0; nt < 8; nt++) {
                const int n = nt * 8 + qr;
                unsigned b[2] = {
                    __float_as_uint(Vs[(ks * 8 + qc) * APAD + n]),
                    __float_as_uint(Vs[(ks * 8 + qc + 4) * APAD + n])
                };
                mma_tf32(oacc[nt], a, b);
            }
        }
        __syncwarp();
    }

    rs0 += __shfl_xor_sync(0xffffffffu, rs0, 1);
    rs0 += __shfl_xor_sync(0xffffffffu, rs0, 2);
    rs1 += __shfl_xor_sync(0xffffffffu, rs1, 1);
    rs1 += __shfl_xor_sync(0xffffffffu, rs1, 2);
    const float inv0 = 1.f / rs0;
    const float inv1 = 1.f / rs1;

#pragma unroll
    for (int nt = 0; nt < 8; nt++) {
        const int col = h * HEAD_DIM + nt * 8 + 2 * qc;
        float x00 = oacc[nt][0] * inv0, x01 = oacc[nt][1] * inv0;
        float x10 = oacc[nt][2] * inv1, x11 = oacc[nt][3] * inv1;
        __nv_bfloat16 h00 = __float2bfloat16(x00), h01 = __float2bfloat16(x01);
        __nv_bfloat16 h10 = __float2bfloat16(x10), h11 = __float2bfloat16(x11);
        *(__nv_bfloat162*)(Oh + (size_t)i0 * D_MODEL + col) = __nv_bfloat162(h00, h01);
        *(__nv_bfloat162*)(Oh + (size_t)i1 * D_MODEL + col) = __nv_bfloat162(h10, h11);
        *(__nv_bfloat162*)(Ol + (size_t)i0 * D_MODEL + col) = __nv_bfloat162(
            __float2bfloat16(x00 - __bfloat162float(h00)), __float2bfloat16(x01 - __bfloat162float(h01)));
        *(__nv_bfloat162*)(Ol + (size_t)i1 * D_MODEL + col) = __nv_bfloat162(
            __float2bfloat16(x10 - __bfloat162float(h10)), __float2bfloat16(x11 - __bfloat162float(h11)));
    }
}

// ---------------------------------------------------------------------------
// Launch
// ---------------------------------------------------------------------------
extern "C" void kernel_launch(void* const* d_in, const int* in_sizes, int n_in,
                              void* d_out, int out_size)
{
    const float* X  = (const float*)d_in[0];
    const float* Wq = (const float*)d_in[1];
    const float* Wk = (const float*)d_in[2];
    const float* Wv = (const float*)d_in[3];
    const float* Wo = (const float*)d_in[4];
    float* out = (float*)d_out;

    float* Qb;  cudaGetSymbolAddress((void**)&Qb, g_Q);
    float* Kb;  cudaGetSymbolAddress((void**)&Kb, g_K);
    float* Vb;  cudaGetSymbolAddress((void**)&Vb, g_V);
    __nv_bfloat16 *Xh, *Xl, *Wh, *Wl, *Woh, *Wol, *Oh, *Ol;
    cudaGetSymbolAddress((void**)&Xh,  g_Xh);
    cudaGetSymbolAddress((void**)&Xl,  g_Xl);
    cudaGetSymbolAddress((void**)&Wh,  g_Wh);
    cudaGetSymbolAddress((void**)&Wl,  g_Wl);
    cudaGetSymbolAddress((void**)&Woh, g_Woh);
    cudaGetSymbolAddress((void**)&Wol, g_Wol);
    cudaGetSymbolAddress((void**)&Oh,  g_Oh);
    cudaGetSymbolAddress((void**)&Ol,  g_Ol);

    static bool attr_set = false;
    if (!attr_set) {
        cudaFuncSetAttribute(gemm_bf3, cudaFuncAttributeMaxDynamicSharedMemorySize, GEMM_SMEM);
        cudaFuncSetAttribute(attn_mma, cudaFuncAttributeMaxDynamicSharedMemorySize, ATTN_SMEM);
        attr_set = true;
    }

    const int SB = 256;
    split_bf<<<(T_SEQ * D_MODEL / 4 + SB - 1) / SB, SB>>>(X, Xh, Xl, T_SEQ * D_MODEL / 4);
    split_bf<<<(D_MODEL * D_MODEL / 4 + SB - 1) / SB, SB>>>(Wq, Wh, Wl, D_MODEL * D_MODEL / 4);
    split_bf<<<(KV_DIM * D_MODEL / 4 + SB - 1) / SB, SB>>>(
        Wk, Wh + (size_t)D_MODEL * D_MODEL, Wl + (size_t)D_MODEL * D_MODEL, KV_DIM * D_MODEL / 4);
    split_bf<<<(KV_DIM * D_MODEL / 4 + SB - 1) / SB, SB>>>(
        Wv, Wh + (size_t)(D_MODEL + KV_DIM) * D_MODEL, Wl + (size_t)(D_MODEL + KV_DIM) * D_MODEL,
        KV_DIM * D_MODEL / 4);
    split_bf<<<(D_MODEL * D_MODEL / 4 + SB - 1) / SB, SB>>>(Wo, Woh, Wol, D_MODEL * D_MODEL / 4);

    rope_tables<<<(T_SEQ * 32 + 255) / 256, 256>>>();

    gemm_bf3<<<dim3(QKV_N / BN, T_SEQ / BM), 256, GEMM_SMEM>>>(
        Xh, Xl, Wh, Wl, D_MODEL,
        Qb, D_MODEL, D_MODEL,
        Kb, D_MODEL + KV_DIM, KV_DIM,
        Vb, KV_DIM);

    rope_apply<<<(T_SEQ * N_HEADS * 32 + 255) / 256, 256>>>(Qb, N_HEADS);
    rope_apply<<<(T_SEQ * N_KV    * 32 + 255) / 256, 256>>>(Kb, N_KV);

    attn_mma<<<dim3(T_SEQ / QT, N_HEADS), 128, ATTN_SMEM>>>(Qb, Kb, Vb, Oh, Ol);

    gemm_bf3<<<dim3(D_MODEL / BN, T_SEQ / BM), 256, GEMM_SMEM>>>(
        Oh, Ol, Woh, Wol, D_MODEL,
        out, D_MODEL, D_MODEL,
        out, D_MODEL + 1, D_MODEL,
        out, D_MODEL);
}

// round 7
// speedup vs baseline: 3.8672x; 1.0375x over previous
#include <cuda_runtime.h>
#include <cuda_bf16.h>
#include <math.h>
#include <stdint.h>

// ---------------------------------------------------------------------------
// Problem constants
// ---------------------------------------------------------------------------
#define T_SEQ    2048
#define D_MODEL  2048
#define N_HEADS  32
#define N_KV     8
#define HEAD_DIM 64
#define KV_DIM   (N_KV * HEAD_DIM)       // 512
#define QKV_N    (D_MODEL + 2 * KV_DIM)  // 3072
#define WINDOW_HALF 256

// ---------------------------------------------------------------------------
// Scratch (device globals; no allocation allowed)
// ---------------------------------------------------------------------------
__device__ float g_Q[(size_t)T_SEQ * D_MODEL];     // 16 MB
__device__ float g_K[(size_t)T_SEQ * KV_DIM];      // 4 MB
__device__ float g_V[(size_t)T_SEQ * KV_DIM];      // 4 MB
__device__ __nv_bfloat16 g_Xh[(size_t)T_SEQ * D_MODEL];
__device__ __nv_bfloat16 g_Xl[(size_t)T_SEQ * D_MODEL];
__device__ __nv_bfloat16 g_Wh[(size_t)QKV_N * D_MODEL];
__device__ __nv_bfloat16 g_Wl[(size_t)QKV_N * D_MODEL];
__device__ __nv_bfloat16 g_Woh[(size_t)D_MODEL * D_MODEL];
__device__ __nv_bfloat16 g_Wol[(size_t)D_MODEL * D_MODEL];
__device__ __nv_bfloat16 g_Oh[(size_t)T_SEQ * D_MODEL];
__device__ __nv_bfloat16 g_Ol[(size_t)T_SEQ * D_MODEL];
__device__ float g_cos[T_SEQ * 32];
__device__ float g_sin[T_SEQ * 32];

// ---------------------------------------------------------------------------
// helpers
// ---------------------------------------------------------------------------
__device__ __forceinline__ unsigned smem_u32(const void* p)
{
    unsigned a;
    asm("{ .reg .u64 t; cvta.to.shared.u64 t, %1; cvt.u32.u64 %0, t; }" : "=r"(a) : "l"(p));
    return a;
}

__device__ __forceinline__ unsigned cvt_tf32(float x)
{
    unsigned r;
    asm("cvt.rna.tf32.f32 %0, %1;" : "=r"(r) : "f"(x));
    return r;
}
__device__ __forceinline__ float tf32f(float x) { return __uint_as_float(cvt_tf32(x)); }

__device__ __forceinline__ void mma_tf32(float* c, const unsigned* a, const unsigned* b)
{
    asm volatile(
        "mma.sync.aligned.m16n8k8.row.col.f32.tf32.tf32.f32 "
        "{%0,%1,%2,%3}, {%4,%5,%6,%7}, {%8,%9}, {%0,%1,%2,%3};"
        : "+f"(c[0]), "+f"(c[1]), "+f"(c[2]), "+f"(c[3])
        : "r"(a[0]), "r"(a[1]), "r"(a[2]), "r"(a[3]),
          "r"(b[0]), "r"(b[1]));
}

__device__ __forceinline__ void mma_bf16(float* c, const unsigned* a, const unsigned* b)
{
    asm volatile(
        "mma.sync.aligned.m16n8k16.row.col.f32.bf16.bf16.f32 "
        "{%0,%1,%2,%3}, {%4,%5,%6,%7}, {%8,%9}, {%0,%1,%2,%3};"
        : "+f"(c[0]), "+f"(c[1]), "+f"(c[2]), "+f"(c[3])
        : "r"(a[0]), "r"(a[1]), "r"(a[2]), "r"(a[3]),
          "r"(b[0]), "r"(b[1]));
}

__device__ __forceinline__ void ldsm_x4(unsigned* r, unsigned addr)
{
    asm volatile("ldmatrix.sync.aligned.m8n8.x4.shared.b16 {%0,%1,%2,%3}, [%4];"
                 : "=r"(r[0]), "=r"(r[1]), "=r"(r[2]), "=r"(r[3]) : "r"(addr));
}

__device__ __forceinline__ void cp16(unsigned dst, const void* src)
{
    asm volatile("cp.async.ca.shared.global [%0], [%1], 16;" :: "r"(dst), "l"(src));
}

// ---------------------------------------------------------------------------
// Fused split: fp32 -> bf16 hi/lo planes for X, Wq, Wk, Wv, Wo in ONE launch.
// ---------------------------------------------------------------------------
#define N4_X   (T_SEQ * D_MODEL / 4)
#define N4_WQ  (D_MODEL * D_MODEL / 4)
#define N4_WKV (KV_DIM * D_MODEL / 4)
#define N4_WO  (D_MODEL * D_MODEL / 4)
#define N4_TOT (N4_X + N4_WQ + 2 * N4_WKV + N4_WO)

__global__ void split_all(const float* __restrict__ X,  const float* __restrict__ Wq,
                          const float* __restrict__ Wk, const float* __restrict__ Wv,
                          const float* __restrict__ Wo,
                          __nv_bfloat16* __restrict__ Xh,  __nv_bfloat16* __restrict__ Xl,
                          __nv_bfloat16* __restrict__ Wh,  __nv_bfloat16* __restrict__ Wl,
                          __nv_bfloat16* __restrict__ Woh, __nv_bfloat16* __restrict__ Wol)
{
    int i = blockIdx.x * blockDim.x + threadIdx.x;
    if (i >= N4_TOT) return;

    const float* s; __nv_bfloat16 *hp, *lp; int off;
    if (i < N4_X)                         { off = i;                           s = X;  hp = Xh;  lp = Xl; }
    else if (i < N4_X + N4_WQ)            { off = i - N4_X;                    s = Wq; hp = Wh;  lp = Wl; }
    else if (i < N4_X + N4_WQ + N4_WKV)   { off = i - N4_X - N4_WQ;            s = Wk;
                                            hp = Wh + (size_t)D_MODEL * D_MODEL;
                                            lp = Wl + (size_t)D_MODEL * D_MODEL; }
    else if (i < N4_X + N4_WQ + 2*N4_WKV) { off = i - N4_X - N4_WQ - N4_WKV;   s = Wv;
                                            hp = Wh + (size_t)(D_MODEL + KV_DIM) * D_MODEL;
                                            lp = Wl + (size_t)(D_MODEL + KV_DIM) * D_MODEL; }
    else                                  { off = i - N4_X - N4_WQ - 2*N4_WKV; s = Wo; hp = Woh; lp = Wol; }

    float4 v = ((const float4*)s)[off];
    float x[4] = {v.x, v.y, v.z, v.w};
    __nv_bfloat16 h[4], l[4];
#pragma unroll
    for (int j = 0; j < 4; j++) {
        h[j] = __float2bfloat16(x[j]);
        l[j] = __float2bfloat16(x[j] - __bfloat162float(h[j]));
    }
    __nv_bfloat162* hq = (__nv_bfloat162*)hp;
    __nv_bfloat162* lq = (__nv_bfloat162*)lp;
    hq[2 * off]     = __nv_bfloat162(h[0], h[1]);
    hq[2 * off + 1] = __nv_bfloat162(h[2], h[3]);
    lq[2 * off]     = __nv_bfloat162(l[0], l[1]);
    lq[2 * off + 1] = __nv_bfloat162(l[2], l[3]);
}

// ---------------------------------------------------------------------------
// bf16x3-split tensor-core GEMM with ldmatrix fragment loads.
//   C[M,N] = A[M,K] * B[N,K]^T
// Block 128x128x32, 256 threads (8 warps, warp tile 64x32), 2-stage cp.async.
// Planes hi/lo separate; rows padded to 40 bf16 (80 B) -> conflict-free LDSM.
// ---------------------------------------------------------------------------
#define BM 128
#define BN 128
#define GBK 32
#define KPAD 40
#define PLANE_E (128 * KPAD)             // bf16 elems per plane tile
#define PLANE_BYTES (PLANE_E * 2)        // 10240
#define STAGE_E (4 * PLANE_E)
#define STAGE_B (STAGE_E * 2)            // 40960 bytes
#define GEMM_SMEM (2 * STAGE_B)          // 81920 bytes

__device__ __forceinline__ void stage_bf(unsigned sbase,
                                         const __nv_bfloat16* Ah, const __nv_bfloat16* Al,
                                         const __nv_bfloat16* Bh, const __nv_bfloat16* Bl,
                                         int K, int bm, int bn, int k0, int tid)
{
#pragma unroll
    for (int t = 0; t < 8; t++) {
        int id = tid + t * 256;              // 0..2047
        int plane = id >> 9;                 // 0..3
        int r = (id >> 2) & 127;
        int c = id & 3;                      // 16B chunk (8 bf16)
        unsigned dst = sbase + (unsigned)(plane * PLANE_E + r * KPAD + c * 8) * 2u;
        const __nv_bfloat16* src;
        if (plane == 0)      src = Ah + (size_t)(bm + r) * K + k0 + c * 8;
        else if (plane == 1) src = Al + (size_t)(bm + r) * K + k0 + c * 8;
        else if (plane == 2) src = Bh + (size_t)(bn + r) * K + k0 + c * 8;
        else                 src = Bl + (size_t)(bn + r) * K + k0 + c * 8;
        cp16(dst, src);
    }
}

__global__ void __launch_bounds__(256, 2)
gemm_bf3(const __nv_bfloat16* __restrict__ Ah, const __nv_bfloat16* __restrict__ Al,
         const __nv_bfloat16* __restrict__ Bh, const __nv_bfloat16* __restrict__ Bl,
         int K,
         float* __restrict__ C0, int n0, int s0,
         float* __restrict__ C1, int n1, int s1,
         float* __restrict__ C2, int s2)
{
    extern __shared__ __nv_bfloat16 smb[];
    unsigned sbase = smem_u32(smb);

    const int tid = threadIdx.x;
    const int bm = blockIdx.y * BM;
    const int bn = blockIdx.x * BN;

    const int warp = tid >> 5;
    const int lane = tid & 31;
    const int qr = lane >> 2;
    const int qc = lane & 3;
    const int wr = warp >> 2;       // 0..1
    const int wc = warp & 3;        // 0..3

    // ldmatrix per-lane source rows:
    //   matrix index = lane/8; within-matrix row = lane%8
    //   A(mt): rows wr*64 + mt*16 + (mat&1)*8 + lane8, k-off (mat>>1)*8
    //   B(n2): rows wc*32 + n2*16 + (mat&1)*8 + lane8, k-off (mat>>1)*8
    const int lane8 = lane & 7;
    const int mat   = lane >> 3;
    const unsigned a_e = (unsigned)((wr * 64 + (mat & 1) * 8 + lane8) * KPAD + (mat >> 1) * 8);
    const unsigned b_e = (unsigned)((wc * 32 + (mat & 1) * 8 + lane8) * KPAD + (mat >> 1) * 8);

    float acc[4][4][4];
#pragma unroll
    for (int i = 0; i < 4; i++)
#pragma unroll
        for (int j = 0; j < 4; j++)
#pragma unroll
            for (int r = 0; r < 4; r++) acc[i][j][r] = 0.f;

    const int NS = K / GBK;

    stage_bf(sbase, Ah, Al, Bh, Bl, K, bm, bn, 0, tid);
    asm volatile("cp.async.commit_group;" ::: "memory");
    stage_bf(sbase + STAGE_B, Ah, Al, Bh, Bl, K, bm, bn, GBK, tid);
    asm volatile("cp.async.commit_group;" ::: "memory");

    for (int s = 0; s < NS; s++) {
        asm volatile("cp.async.wait_group 1;" ::: "memory");
        __syncthreads();

        const int buf = s & 1;
        const unsigned stg = sbase + buf * STAGE_B;
        const unsigned aH = stg + a_e * 2;
        const unsigned aL = aH + PLANE_BYTES;
        const unsigned bH = stg + 2 * PLANE_BYTES + b_e * 2;
        const unsigned bL = bH + PLANE_BYTES;

#pragma unroll
        for (int ks = 0; ks < GBK; ks += 16) {
            // B fragments: one x4 covers two n-tiles' full k16 frags
            unsigned bh[2][4], bl[2][4];
#pragma unroll
            for (int n2 = 0; n2 < 2; n2++) {
                ldsm_x4(bh[n2], bH + n2 * (16 * KPAD * 2) + ks * 2);
                ldsm_x4(bl[n2], bL + n2 * (16 * KPAD * 2) + ks * 2);
            }
#pragma unroll
            for (int mt = 0; mt < 4; mt++) {
                unsigned ah[4], al[4];
                ldsm_x4(ah, aH + mt * (16 * KPAD * 2) + ks * 2);
                ldsm_x4(al, aL + mt * (16 * KPAD * 2) + ks * 2);
#pragma unroll
                for (int nt = 0; nt < 4; nt++) {
                    const int n2 = nt >> 1, od = nt & 1;
                    unsigned bhf[2] = {bh[n2][od], bh[n2][od + 2]};
                    unsigned blf[2] = {bl[n2][od], bl[n2][od + 2]};
                    mma_bf16(acc[mt][nt], ah, bhf);
                    mma_bf16(acc[mt][nt], ah, blf);
                    mma_bf16(acc[mt][nt], al, bhf);
                }
            }
        }
        __syncthreads();

        if (s + 2 < NS)
            stage_bf(sbase + buf * STAGE_B, Ah, Al, Bh, Bl, K, bm, bn, (s + 2) * GBK, tid);
        asm volatile("cp.async.commit_group;" ::: "memory");
    }

    float* C; int col0, stride;
    if (bn < n0)      { C = C0; col0 = bn;      stride = s0; }
    else if (bn < n1) { C = C1; col0 = bn - n0; stride = s1; }
    else              { C = C2; col0 = bn - n1; stride = s2; }

#pragma unroll
    for (int mt = 0; mt < 4; mt++) {
        const int row0 = bm + wr * 64 + mt * 16 + qr;
#pragma unroll
        for (int nt = 0; nt < 4; nt++) {
            const int col = col0 + wc * 32 + nt * 8 + qc * 2;
            *(float2*)(C + (size_t)row0       * stride + col) = make_float2(acc[mt][nt][0], acc[mt][nt][1]);
            *(float2*)(C + (size_t)(row0 + 8) * stride + col) = make_float2(acc[mt][nt][2], acc[mt][nt][3]);
        }
    }
}

// ---------------------------------------------------------------------------
// RoPE
// ---------------------------------------------------------------------------
__global__ void rope_tables()
{
    int idx = blockIdx.x * blockDim.x + threadIdx.x;
    if (idx >= T_SEQ * 32) return;
    int i = idx & 31;
    int t = idx >> 5;
    double invf = exp2(-(double)i / 32.0 * 13.287712379549449392);
    double ang  = fmod((double)t * invf, 6.28318530717958647692);
    g_cos[idx] = cosf((float)ang);
    g_sin[idx] = sinf((float)ang);
}

__global__ void rope_apply(float* __restrict__ X, int nheads)
{
    int idx = blockIdx.x * blockDim.x + threadIdx.x;
    int total = T_SEQ * nheads * 32;
    if (idx >= total) return;
    int i = idx & 31;
    int h = (idx >> 5) % nheads;
    int t = idx / (32 * nheads);
    float c = g_cos[t * 32 + i];
    float s = g_sin[t * 32 + i];
    float* row = X + (size_t)t * (nheads * HEAD_DIM) + h * HEAD_DIM;
    float x0 = row[i];
    float x1 = row[i + 32];
    row[i]      = x0 * c - x1 * s;
    row[i + 32] = x1 * c + x0 * s;
}

// ---------------------------------------------------------------------------
// Tensor-core banded GQA attention (round-5 kernel, unchanged)
// ---------------------------------------------------------------------------
#define QT   64
#define CHK  64
#define APAD 68
#define ATTN_SMEM (3 * QT * APAD * 4)

__global__ void __launch_bounds__(128)
attn_mma(const float* __restrict__ Q, const float* __restrict__ K,
         const float* __restrict__ V,
         __nv_bfloat16* __restrict__ Oh, __nv_bfloat16* __restrict__ Ol)
{
    extern __shared__ float asm_[];
    float* Qs = asm_;
    float* Ks = asm_ + QT * APAD;
    float* Vs = asm_ + 2 * QT * APAD;

    const int h  = blockIdx.y;
    const int g  = h >> 2;
    const int q0 = blockIdx.x * QT;
    const int tid = threadIdx.x;
    const int w = tid >> 5;
    const int lane = tid & 31;
    const int qr = lane >> 2;
    const int qc = lane & 3;

#pragma unroll
    for (int t = 0; t < 8; t++) {
        int idx = tid + t * 128;
        int r  = idx >> 4;
        int d4 = (idx & 15) * 4;
        float4 v = *(const float4*)(Q + (size_t)(q0 + r) * D_MODEL + h * HEAD_DIM + d4);
        Qs[r * APAD + d4 + 0] = tf32f(v.x);
        Qs[r * APAD + d4 + 1] = tf32f(v.y);
        Qs[r * APAD + d4 + 2] = tf32f(v.z);
        Qs[r * APAD + d4 + 3] = tf32f(v.w);
    }
    __syncthreads();

    unsigned qa[8][4];
    {
        const int m0 = w * 16 + qr;
#pragma unroll
        for (int ks = 0; ks < 8; ks++) {
            qa[ks][0] = __float_as_uint(Qs[m0 * APAD + ks * 8 + qc]);
            qa[ks][1] = __float_as_uint(Qs[(m0 + 8) * APAD + ks * 8 + qc]);
            qa[ks][2] = __float_as_uint(Qs[m0 * APAD + ks * 8 + qc + 4]);
            qa[ks][3] = __float_as_uint(Qs[(m0 + 8) * APAD + ks * 8 + qc + 4]);
        }
    }
    float* Ps = Qs;

    float oacc[8][4];
#pragma unroll
    for (int nt = 0; nt < 8; nt++)
#pragma unroll
        for (int r = 0; r < 4; r++) oacc[nt][r] = 0.f;
    float rs0 = 0.f, rs1 = 0.f;

    const int i0 = q0 + w * 16 + qr;
    const int i1 = i0 + 8;
    const float SC = 0.125f * 1.44269504088896f;

    const int jstart = max(0, q0 - WINDOW_HALF);
    const int jend   = min(T_SEQ, q0 + QT + WINDOW_HALF);

    for (int c = jstart; c < jend; c += CHK) {
        __syncthreads();
#pragma unroll
        for (int t = 0; t < 8; t++) {
            int idx = tid + t * 128;
            int r  = idx >> 4;
            int d4 = (idx & 15) * 4;
            const size_t go = (size_t)(c + r) * KV_DIM + g * HEAD_DIM + d4;
            float4 kv = *(const float4*)(K + go);
            float4 vv = *(const float4*)(V + go);
            Ks[r * APAD + d4 + 0] = tf32f(kv.x);
            Ks[r * APAD + d4 + 1] = tf32f(kv.y);
            Ks[r * APAD + d4 + 2] = tf32f(kv.z);
            Ks[r * APAD + d4 + 3] = tf32f(kv.w);
            Vs[r * APAD + d4 + 0] = tf32f(vv.x);
            Vs[r * APAD + d4 + 1] = tf32f(vv.y);
            Vs[r * APAD + d4 + 2] = tf32f(vv.z);
            Vs[r * APAD + d4 + 3] = tf32f(vv.w);
        }
        __syncthreads();

        float sfr[8][4];
#pragma unroll
        for (int nt = 0; nt < 8; nt++)
#pragma unroll
            for (int r = 0; r < 4; r++) sfr[nt][r] = 0.f;
#pragma unroll
        for (int ks = 0; ks < 8; ks++) {
#pragma unroll
            for (int nt = 0; nt < 8; nt++) {
                const int n = nt * 8 + qr;
                unsigned b[2] = {
                    __float_as_uint(Ks[n * APAD + ks * 8 + qc]),
                    __float_as_uint(Ks[n * APAD + ks * 8 + qc + 4])
                };
                mma_tf32(sfr[nt], qa[ks], b);
            }
        }

        const int m0 = w * 16 + qr;
#pragma unroll
        for (int nt = 0; nt < 8; nt++) {
            const int j0 = c + nt * 8 + 2 * qc;
            const int j1 = j0 + 1;
            float p00 = (j0 >= i0 - WINDOW_HALF && j0 < i0 + WINDOW_HALF) ? exp2f(sfr[nt][0] * SC) : 0.f;
            float p01 = (j1 >= i0 - WINDOW_HALF && j1 < i0 + WINDOW_HALF) ? exp2f(sfr[nt][1] * SC) : 0.f;
            float p10 = (j0 >= i1 - WINDOW_HALF && j0 < i1 + WINDOW_HALF) ? exp2f(sfr[nt][2] * SC) : 0.f;
            float p11 = (j1 >= i1 - WINDOW_HALF && j1 < i1 + WINDOW_HALF) ? exp2f(sfr[nt][3] * SC) : 0.f;
            rs0 += p00 + p01;
            rs1 += p10 + p11;
            *(float2*)&Ps[m0 * APAD + nt * 8 + 2 * qc]       = make_float2(tf32f(p00), tf32f(p01));
            *(float2*)&Ps[(m0 + 8) * APAD + nt * 8 + 2 * qc] = make_float2(tf32f(p10), tf32f(p11));
        }
        __syncwarp();

#pragma unroll
        for (int ks = 0; ks < 8; ks++) {
            unsigned a[4] = {
                __float_as_uint(Ps[m0 * APAD + ks * 8 + qc]),
                __float_as_uint(Ps[(m0 + 8) * APAD + ks * 8 + qc]),
                __float_as_uint(Ps[m0 * APAD + ks * 8 + qc + 4]),
                __float_as_uint(Ps[(m0 + 8) * APAD + ks * 8 + qc + 4])
            };
#pragma unroll
            for (int nt = 0; nt < 8; nt++) {
                const int n = nt * 8 + qr;
                unsigned b[2] = {
                    __float_as_uint(Vs[(ks * 8 + qc) * APAD + n]),
                    __float_as_uint(Vs[(ks * 8 + qc + 4) * APAD + n])
                };
                mma_tf32(oacc[nt], a, b);
            }
        }
        __syncwarp();
    }

    rs0 += __shfl_xor_sync(0xffffffffu, rs0, 1);
    rs0 += __shfl_xor_sync(0xffffffffu, rs0, 2);
    rs1 += __shfl_xor_sync(0xffffffffu, rs1, 1);
    rs1 += __shfl_xor_sync(0xffffffffu, rs1, 2);
    const float inv0 = 1.f / rs0;
    const float inv1 = 1.f / rs1;

#pragma unroll
    for (int nt = 0; nt < 8; nt++) {
        const int col = h * HEAD_DIM + nt * 8 + 2 * qc;
        float x00 = oacc[nt][0] * inv0, x01 = oacc[nt][1] * inv0;
        float x10 = oacc[nt][2] * inv1, x11 = oacc[nt][3] * inv1;
        __nv_bfloat16 h00 = __float2bfloat16(x00), h01 = __float2bfloat16(x01);
        __nv_bfloat16 h10 = __float2bfloat16(x10), h11 = __float2bfloat16(x11);
        *(__nv_bfloat162*)(Oh + (size_t)i0 * D_MODEL + col) = __nv_bfloat162(h00, h01);
        *(__nv_bfloat162*)(Oh + (size_t)i1 * D_MODEL + col) = __nv_bfloat162(h10, h11);
        *(__nv_bfloat162*)(Ol + (size_t)i0 * D_MODEL + col) = __nv_bfloat162(
            __float2bfloat16(x00 - __bfloat162float(h00)), __float2bfloat16(x01 - __bfloat162float(h01)));
        *(__nv_bfloat162*)(Ol + (size_t)i1 * D_MODEL + col) = __nv_bfloat162(
            __float2bfloat16(x10 - __bfloat162float(h10)), __float2bfloat16(x11 - __bfloat162float(h11)));
    }
}

// ---------------------------------------------------------------------------
// Launch
// ---------------------------------------------------------------------------
extern "C" void kernel_launch(void* const* d_in, const int* in_sizes, int n_in,
                              void* d_out, int out_size)
{
    const float* X  = (const float*)d_in[0];
    const float* Wq = (const float*)d_in[1];
    const float* Wk = (const float*)d_in[2];
    const float* Wv = (const float*)d_in[3];
    const float* Wo = (const float*)d_in[4];
    float* out = (float*)d_out;

    float* Qb;  cudaGetSymbolAddress((void**)&Qb, g_Q);
    float* Kb;  cudaGetSymbolAddress((void**)&Kb, g_K);
    float* Vb;  cudaGetSymbolAddress((void**)&Vb, g_V);
    __nv_bfloat16 *Xh, *Xl, *Wh, *Wl, *Woh, *Wol, *Oh, *Ol;
    cudaGetSymbolAddress((void**)&Xh,  g_Xh);
    cudaGetSymbolAddress((void**)&Xl,  g_Xl);
    cudaGetSymbolAddress((void**)&Wh,  g_Wh);
    cudaGetSymbolAddress((void**)&Wl,  g_Wl);
    cudaGetSymbolAddress((void**)&Woh, g_Woh);
    cudaGetSymbolAddress((void**)&Wol, g_Wol);
    cudaGetSymbolAddress((void**)&Oh,  g_Oh);
    cudaGetSymbolAddress((void**)&Ol,  g_Ol);

    static bool attr_set = false;
    if (!attr_set) {
        cudaFuncSetAttribute(gemm_bf3, cudaFuncAttributeMaxDynamicSharedMemorySize, GEMM_SMEM);
        cudaFuncSetAttribute(attn_mma, cudaFuncAttributeMaxDynamicSharedMemorySize, ATTN_SMEM);
        attr_set = true;
    }

    split_all<<<(N4_TOT + 255) / 256, 256>>>(X, Wq, Wk, Wv, Wo, Xh, Xl, Wh, Wl, Woh, Wol);

    rope_tables<<<(T_SEQ * 32 + 255) / 256, 256>>>();

    gemm_bf3<<<dim3(QKV_N / BN, T_SEQ / BM), 256, GEMM_SMEM>>>(
        Xh, Xl, Wh, Wl, D_MODEL,
        Qb, D_MODEL, D_MODEL,
        Kb, D_MODEL + KV_DIM, KV_DIM,
        Vb, KV_DIM);

    rope_apply<<<(T_SEQ * N_HEADS * 32 + 255) / 256, 256>>>(Qb, N_HEADS);
    rope_apply<<<(T_SEQ * N_KV    * 32 + 255) / 256, 256>>>(Kb, N_KV);

    attn_mma<<<dim3(T_SEQ / QT, N_HEADS), 128, ATTN_SMEM>>>(Qb, Kb, Vb, Oh, Ol);

    gemm_bf3<<<dim3(D_MODEL / BN, T_SEQ / BM), 256, GEMM_SMEM>>>(
        Oh, Ol, Woh, Wol, D_MODEL,
        out, D_MODEL, D_MODEL,
        out, D_MODEL + 1, D_MODEL,
        out, D_MODEL);
}

// round 8
// speedup vs baseline: 5.0622x; 1.3090x over previous
#include <cuda_runtime.h>
#include <cuda_bf16.h>
#include <cuda_fp16.h>
#include <math.h>
#include <stdint.h>

// ---------------------------------------------------------------------------
// Problem constants
// ---------------------------------------------------------------------------
#define T_SEQ    2048
#define D_MODEL  2048
#define N_HEADS  32
#define N_KV     8
#define HEAD_DIM 64
#define KV_DIM   (N_KV * HEAD_DIM)       // 512
#define QKV_N    (D_MODEL + 2 * KV_DIM)  // 3072
#define WINDOW_HALF 256

// ---------------------------------------------------------------------------
// Scratch (device globals; no allocation allowed)
// ---------------------------------------------------------------------------
__device__ float  g_Q[(size_t)T_SEQ * D_MODEL];     // 16 MB
__device__ float  g_K[(size_t)T_SEQ * KV_DIM];      // 4 MB
__device__ float  g_V[(size_t)T_SEQ * KV_DIM];      // 4 MB
__device__ __half g_Xh[(size_t)T_SEQ * D_MODEL];
__device__ __half g_Wh[(size_t)QKV_N * D_MODEL];
__device__ __half g_Wl[(size_t)QKV_N * D_MODEL];
__device__ __half g_Woh[(size_t)D_MODEL * D_MODEL];
__device__ __half g_Wol[(size_t)D_MODEL * D_MODEL];
__device__ __half g_Oh[(size_t)T_SEQ * D_MODEL];
__device__ float  g_cos[T_SEQ * 32];
__device__ float  g_sin[T_SEQ * 32];

// ---------------------------------------------------------------------------
// helpers
// ---------------------------------------------------------------------------
__device__ __forceinline__ unsigned smem_u32(const void* p)
{
    unsigned a;
    asm("{ .reg .u64 t; cvta.to.shared.u64 t, %1; cvt.u32.u64 %0, t; }" : "=r"(a) : "l"(p));
    return a;
}

__device__ __forceinline__ unsigned cvt_tf32(float x)
{
    unsigned r;
    asm("cvt.rna.tf32.f32 %0, %1;" : "=r"(r) : "f"(x));
    return r;
}
__device__ __forceinline__ float tf32f(float x) { return __uint_as_float(cvt_tf32(x)); }

__device__ __forceinline__ void mma_tf32(float* c, const unsigned* a, const unsigned* b)
{
    asm volatile(
        "mma.sync.aligned.m16n8k8.row.col.f32.tf32.tf32.f32 "
        "{%0,%1,%2,%3}, {%4,%5,%6,%7}, {%8,%9}, {%0,%1,%2,%3};"
        : "+f"(c[0]), "+f"(c[1]), "+f"(c[2]), "+f"(c[3])
        : "r"(a[0]), "r"(a[1]), "r"(a[2]), "r"(a[3]),
          "r"(b[0]), "r"(b[1]));
}

__device__ __forceinline__ void mma_fp16(float* c, const unsigned* a, const unsigned* b)
{
    asm volatile(
        "mma.sync.aligned.m16n8k16.row.col.f32.f16.f16.f32 "
        "{%0,%1,%2,%3}, {%4,%5,%6,%7}, {%8,%9}, {%0,%1,%2,%3};"
        : "+f"(c[0]), "+f"(c[1]), "+f"(c[2]), "+f"(c[3])
        : "r"(a[0]), "r"(a[1]), "r"(a[2]), "r"(a[3]),
          "r"(b[0]), "r"(b[1]));
}

__device__ __forceinline__ void ldsm_x4(unsigned* r, unsigned addr)
{
    asm volatile("ldmatrix.sync.aligned.m8n8.x4.shared.b16 {%0,%1,%2,%3}, [%4];"
                 : "=r"(r[0]), "=r"(r[1]), "=r"(r[2]), "=r"(r[3]) : "r"(addr));
}

__device__ __forceinline__ void cp16(unsigned dst, const void* src)
{
    asm volatile("cp.async.ca.shared.global [%0], [%1], 16;" :: "r"(dst), "l"(src));
}

// ---------------------------------------------------------------------------
// Fused split: X -> fp16; Wq/Wk/Wv -> fp16 hi/lo; Wo -> fp16 hi/lo. One launch.
// ---------------------------------------------------------------------------
#define N4_X   (T_SEQ * D_MODEL / 4)
#define N4_WQ  (D_MODEL * D_MODEL / 4)
#define N4_WKV (KV_DIM * D_MODEL / 4)
#define N4_WO  (D_MODEL * D_MODEL / 4)
#define N4_TOT (N4_X + N4_WQ + 2 * N4_WKV + N4_WO)

__global__ void split_all(const float* __restrict__ X,  const float* __restrict__ Wq,
                          const float* __restrict__ Wk, const float* __restrict__ Wv,
                          const float* __restrict__ Wo,
                          __half* __restrict__ Xh,
                          __half* __restrict__ Wh,  __half* __restrict__ Wl,
                          __half* __restrict__ Woh, __half* __restrict__ Wol)
{
    int i = blockIdx.x * blockDim.x + threadIdx.x;
    if (i >= N4_TOT) return;

    const float* s; __half *hp, *lp; int off; bool has_lo = true;
    if (i < N4_X)                         { off = i;                           s = X;  hp = Xh;  lp = 0; has_lo = false; }
    else if (i < N4_X + N4_WQ)            { off = i - N4_X;                    s = Wq; hp = Wh;  lp = Wl; }
    else if (i < N4_X + N4_WQ + N4_WKV)   { off = i - N4_X - N4_WQ;            s = Wk;
                                            hp = Wh + (size_t)D_MODEL * D_MODEL;
                                            lp = Wl + (size_t)D_MODEL * D_MODEL; }
    else if (i < N4_X + N4_WQ + 2*N4_WKV) { off = i - N4_X - N4_WQ - N4_WKV;   s = Wv;
                                            hp = Wh + (size_t)(D_MODEL + KV_DIM) * D_MODEL;
                                            lp = Wl + (size_t)(D_MODEL + KV_DIM) * D_MODEL; }
    else                                  { off = i - N4_X - N4_WQ - 2*N4_WKV; s = Wo; hp = Woh; lp = Wol; }

    float4 v = ((const float4*)s)[off];
    float x[4] = {v.x, v.y, v.z, v.w};
    __half h[4], l[4];
#pragma unroll
    for (int j = 0; j < 4; j++) {
        h[j] = __float2half_rn(x[j]);
        l[j] = __float2half_rn(x[j] - __half2float(h[j]));
    }
    __half2* hq = (__half2*)hp;
    hq[2 * off]     = __halves2half2(h[0], h[1]);
    hq[2 * off + 1] = __halves2half2(h[2], h[3]);
    if (has_lo) {
        __half2* lq = (__half2*)lp;
        lq[2 * off]     = __halves2half2(l[0], l[1]);
        lq[2 * off + 1] = __halves2half2(l[2], l[3]);
    }
}

// ---------------------------------------------------------------------------
// fp16 2-pass tensor-core GEMM:  C[M,N] = A[M,K] * (Bh+Bl)[N,K]^T
// A single fp16 plane; B split hi/lo. Block 128x128x32, 256 thr, 8 warps,
// warp tile 64x32, 2-stage cp.async, ldmatrix fragment loads.
// ---------------------------------------------------------------------------
#define BM 128
#define BN 128
#define GBK 32
#define KPAD 40
#define PLANE_E (128 * KPAD)
#define PLANE_BYTES (PLANE_E * 2)        // 10240
#define STAGE_E (3 * PLANE_E)            // A, Bh, Bl
#define STAGE_B (STAGE_E * 2)            // 30720 bytes
#define GEMM_SMEM (2 * STAGE_B)          // 61440 bytes

__device__ __forceinline__ void stage_fp(unsigned sbase,
                                         const __half* A, const __half* Bh, const __half* Bl,
                                         int K, int bm, int bn, int k0, int tid)
{
#pragma unroll
    for (int t = 0; t < 6; t++) {
        int id = tid + t * 256;              // 0..1535
        int plane = id >> 9;                 // 0..2
        int r = (id >> 2) & 127;
        int c = id & 3;                      // 16B chunk (8 fp16)
        unsigned dst = sbase + (unsigned)(plane * PLANE_E + r * KPAD + c * 8) * 2u;
        const __half* src;
        if (plane == 0)      src = A  + (size_t)(bm + r) * K + k0 + c * 8;
        else if (plane == 1) src = Bh + (size_t)(bn + r) * K + k0 + c * 8;
        else                 src = Bl + (size_t)(bn + r) * K + k0 + c * 8;
        cp16(dst, src);
    }
}

__global__ void __launch_bounds__(256, 2)
gemm_fp2(const __half* __restrict__ A, const __half* __restrict__ Bh,
         const __half* __restrict__ Bl, int K,
         float* __restrict__ C0, int n0, int s0,
         float* __restrict__ C1, int n1, int s1,
         float* __restrict__ C2, int s2)
{
    extern __shared__ __half smb[];
    unsigned sbase = smem_u32(smb);

    const int tid = threadIdx.x;
    const int bm = blockIdx.y * BM;
    const int bn = blockIdx.x * BN;

    const int warp = tid >> 5;
    const int lane = tid & 31;
    const int qr = lane >> 2;
    const int qc = lane & 3;
    const int wr = warp >> 2;       // 0..1
    const int wc = warp & 3;        // 0..3

    const int lane8 = lane & 7;
    const int mat   = lane >> 3;
    const unsigned a_e = (unsigned)((wr * 64 + (mat & 1) * 8 + lane8) * KPAD + (mat >> 1) * 8);
    const unsigned b_e = (unsigned)((wc * 32 + (mat & 1) * 8 + lane8) * KPAD + (mat >> 1) * 8);

    float acc[4][4][4];
#pragma unroll
    for (int i = 0; i < 4; i++)
#pragma unroll
        for (int j = 0; j < 4; j++)
#pragma unroll
            for (int r = 0; r < 4; r++) acc[i][j][r] = 0.f;

    const int NS = K / GBK;

    stage_fp(sbase, A, Bh, Bl, K, bm, bn, 0, tid);
    asm volatile("cp.async.commit_group;" ::: "memory");
    stage_fp(sbase + STAGE_B, A, Bh, Bl, K, bm, bn, GBK, tid);
    asm volatile("cp.async.commit_group;" ::: "memory");

    for (int s = 0; s < NS; s++) {
        asm volatile("cp.async.wait_group 1;" ::: "memory");
        __syncthreads();

        const int buf = s & 1;
        const unsigned stg = sbase + buf * STAGE_B;
        const unsigned aP = stg + a_e * 2;
        const unsigned bH = stg + PLANE_BYTES + b_e * 2;
        const unsigned bL = bH + PLANE_BYTES;

#pragma unroll
        for (int ks = 0; ks < GBK; ks += 16) {
            unsigned bh[2][4], bl[2][4];
#pragma unroll
            for (int n2 = 0; n2 < 2; n2++) {
                ldsm_x4(bh[n2], bH + n2 * (16 * KPAD * 2) + ks * 2);
                ldsm_x4(bl[n2], bL + n2 * (16 * KPAD * 2) + ks * 2);
            }
#pragma unroll
            for (int mt = 0; mt < 4; mt++) {
                unsigned ah[4];
                ldsm_x4(ah, aP + mt * (16 * KPAD * 2) + ks * 2);
#pragma unroll
                for (int nt = 0; nt < 4; nt++) {
                    const int n2 = nt >> 1, od = nt & 1;
                    unsigned bhf[2] = {bh[n2][od], bh[n2][od + 2]};
                    unsigned blf[2] = {bl[n2][od], bl[n2][od + 2]};
                    mma_fp16(acc[mt][nt], ah, bhf);
                    mma_fp16(acc[mt][nt], ah, blf);
                }
            }
        }
        __syncthreads();

        if (s + 2 < NS)
            stage_fp(sbase + buf * STAGE_B, A, Bh, Bl, K, bm, bn, (s + 2) * GBK, tid);
        asm volatile("cp.async.commit_group;" ::: "memory");
    }

    float* C; int col0, stride;
    if (bn < n0)      { C = C0; col0 = bn;      stride = s0; }
    else if (bn < n1) { C = C1; col0 = bn - n0; stride = s1; }
    else              { C = C2; col0 = bn - n1; stride = s2; }

#pragma unroll
    for (int mt = 0; mt < 4; mt++) {
        const int row0 = bm + wr * 64 + mt * 16 + qr;
#pragma unroll
        for (int nt = 0; nt < 4; nt++) {
            const int col = col0 + wc * 32 + nt * 8 + qc * 2;
            *(float2*)(C + (size_t)row0       * stride + col) = make_float2(acc[mt][nt][0], acc[mt][nt][1]);
            *(float2*)(C + (size_t)(row0 + 8) * stride + col) = make_float2(acc[mt][nt][2], acc[mt][nt][3]);
        }
    }
}

// ---------------------------------------------------------------------------
// RoPE tables (rope application is fused into the attention kernel)
// ---------------------------------------------------------------------------
__global__ void rope_tables()
{
    int idx = blockIdx.x * blockDim.x + threadIdx.x;
    if (idx >= T_SEQ * 32) return;
    int i = idx & 31;
    int t = idx >> 5;
    double invf = exp2(-(double)i / 32.0 * 13.287712379549449392);
    double ang  = fmod((double)t * invf, 6.28318530717958647692);
    g_cos[idx] = cosf((float)ang);
    g_sin[idx] = sinf((float)ang);
}

// ---------------------------------------------------------------------------
// Tensor-core banded GQA attention with fused RoPE.
// Block = 64-query tile x 1 head, 128 threads. RoPE applied to Q and K while
// staging into smem. Output written as single fp16 plane.
// ---------------------------------------------------------------------------
#define QT   64
#define CHK  64
#define APAD 68
#define ATTN_SMEM (3 * QT * APAD * 4)

__global__ void __launch_bounds__(128)
attn_mma(const float* __restrict__ Q, const float* __restrict__ K,
         const float* __restrict__ V, __half* __restrict__ Oh)
{
    extern __shared__ float asm_[];
    float* Qs = asm_;
    float* Ks = asm_ + QT * APAD;
    float* Vs = asm_ + 2 * QT * APAD;

    const int h  = blockIdx.y;
    const int g  = h >> 2;
    const int q0 = blockIdx.x * QT;
    const int tid = threadIdx.x;
    const int w = tid >> 5;
    const int lane = tid & 31;
    const int qr = lane >> 2;
    const int qc = lane & 3;

    // stage Q tile with RoPE (pairs d, d+32), tf32-rounded
#pragma unroll
    for (int t = 0; t < 4; t++) {
        int idx = tid + t * 128;          // 0..511
        int r  = idx >> 3;                // 0..63
        int d4 = (idx & 7) * 4;           // 0..28
        const float* qp = Q + (size_t)(q0 + r) * D_MODEL + h * HEAD_DIM;
        float4 a  = *(const float4*)(qp + d4);
        float4 b  = *(const float4*)(qp + d4 + 32);
        float4 cs = *(const float4*)(g_cos + (q0 + r) * 32 + d4);
        float4 sn = *(const float4*)(g_sin + (q0 + r) * 32 + d4);
        Qs[r * APAD + d4 + 0]  = tf32f(a.x * cs.x - b.x * sn.x);
        Qs[r * APAD + d4 + 1]  = tf32f(a.y * cs.y - b.y * sn.y);
        Qs[r * APAD + d4 + 2]  = tf32f(a.z * cs.z - b.z * sn.z);
        Qs[r * APAD + d4 + 3]  = tf32f(a.w * cs.w - b.w * sn.w);
        Qs[r * APAD + d4 + 32] = tf32f(b.x * cs.x + a.x * sn.x);
        Qs[r * APAD + d4 + 33] = tf32f(b.y * cs.y + a.y * sn.y);
        Qs[r * APAD + d4 + 34] = tf32f(b.z * cs.z + a.z * sn.z);
        Qs[r * APAD + d4 + 35] = tf32f(b.w * cs.w + a.w * sn.w);
    }
    __syncthreads();

    unsigned qa[8][4];
    {
        const int m0 = w * 16 + qr;
#pragma unroll
        for (int ks = 0; ks < 8; ks++) {
            qa[ks][0] = __float_as_uint(Qs[m0 * APAD + ks * 8 + qc]);
            qa[ks][1] = __float_as_uint(Qs[(m0 + 8) * APAD + ks * 8 + qc]);
            qa[ks][2] = __float_as_uint(Qs[m0 * APAD + ks * 8 + qc + 4]);
            qa[ks][3] = __float_as_uint(Qs[(m0 + 8) * APAD + ks * 8 + qc + 4]);
        }
    }
    float* Ps = Qs;

    float oacc[8][4];
#pragma unroll
    for (int nt = 0; nt < 8; nt++)
#pragma unroll
        for (int r = 0; r < 4; r++) oacc[nt][r] = 0.f;
    float rs0 = 0.f, rs1 = 0.f;

    const int i0 = q0 + w * 16 + qr;
    const int i1 = i0 + 8;
    const float SC = 0.125f * 1.44269504088896f;

    const int jstart = max(0, q0 - WINDOW_HALF);
    const int jend   = min(T_SEQ, q0 + QT + WINDOW_HALF);

    for (int c = jstart; c < jend; c += CHK) {
        __syncthreads();
        // stage K (with RoPE) and V chunks, tf32-rounded
#pragma unroll
        for (int t = 0; t < 2; t++) {
            int idx = tid + t * 128;       // 0..255
            int r  = idx >> 2;             // 0..63
            int d4 = (idx & 3) * 8;        // 0,8,16,24
#pragma unroll
            for (int half = 0; half < 2; half++) {
                int d = d4 + half * 4;     // 0..28
                const size_t go = (size_t)(c + r) * KV_DIM + g * HEAD_DIM + d;
                float4 a  = *(const float4*)(K + go);
                float4 b  = *(const float4*)(K + go + 32);
                float4 cs = *(const float4*)(g_cos + (c + r) * 32 + d);
                float4 sn = *(const float4*)(g_sin + (c + r) * 32 + d);
                Ks[r * APAD + d + 0]  = tf32f(a.x * cs.x - b.x * sn.x);
                Ks[r * APAD + d + 1]  = tf32f(a.y * cs.y - b.y * sn.y);
                Ks[r * APAD + d + 2]  = tf32f(a.z * cs.z - b.z * sn.z);
                Ks[r * APAD + d + 3]  = tf32f(a.w * cs.w - b.w * sn.w);
                Ks[r * APAD + d + 32] = tf32f(b.x * cs.x + a.x * sn.x);
                Ks[r * APAD + d + 33] = tf32f(b.y * cs.y + a.y * sn.y);
                Ks[r * APAD + d + 34] = tf32f(b.z * cs.z + a.z * sn.z);
                Ks[r * APAD + d + 35] = tf32f(b.w * cs.w + a.w * sn.w);
                float4 v0 = *(const float4*)(V + go);
                float4 v1 = *(const float4*)(V + go + 32);
                Vs[r * APAD + d + 0]  = tf32f(v0.x);
                Vs[r * APAD + d + 1]  = tf32f(v0.y);
                Vs[r * APAD + d + 2]  = tf32f(v0.z);
                Vs[r * APAD + d + 3]  = tf32f(v0.w);
                Vs[r * APAD + d + 32] = tf32f(v1.x);
                Vs[r * APAD + d + 33] = tf32f(v1.y);
                Vs[r * APAD + d + 34] = tf32f(v1.z);
                Vs[r * APAD + d + 35] = tf32f(v1.w);
            }
        }
        __syncthreads();

        float sfr[8][4];
#pragma unroll
        for (int nt = 0; nt < 8; nt++)
#pragma unroll
            for (int r = 0; r < 4; r++) sfr[nt][r] = 0.f;
#pragma unroll
        for (int ks = 0; ks < 8; ks++) {
#pragma unroll
            for (int nt = 0; nt < 8; nt++) {
                const int n = nt * 8 + qr;
                unsigned b[2] = {
                    __float_as_uint(Ks[n * APAD + ks * 8 + qc]),
                    __float_as_uint(Ks[n * APAD + ks * 8 + qc + 4])
                };
                mma_tf32(sfr[nt], qa[ks], b);
            }
        }

        const int m0 = w * 16 + qr;
#pragma unroll
        for (int nt = 0; nt < 8; nt++) {
            const int j0 = c + nt * 8 + 2 * qc;
            const int j1 = j0 + 1;
            float p00 = (j0 >= i0 - WINDOW_HALF && j0 < i0 + WINDOW_HALF) ? exp2f(sfr[nt][0] * SC) : 0.f;
            float p01 = (j1 >= i0 - WINDOW_HALF && j1 < i0 + WINDOW_HALF) ? exp2f(sfr[nt][1] * SC) : 0.f;
            float p10 = (j0 >= i1 - WINDOW_HALF && j0 < i1 + WINDOW_HALF) ? exp2f(sfr[nt][2] * SC) : 0.f;
            float p11 = (j1 >= i1 - WINDOW_HALF && j1 < i1 + WINDOW_HALF) ? exp2f(sfr[nt][3] * SC) : 0.f;
            rs0 += p00 + p01;
            rs1 += p10 + p11;
            *(float2*)&Ps[m0 * APAD + nt * 8 + 2 * qc]       = make_float2(tf32f(p00), tf32f(p01));
            *(float2*)&Ps[(m0 + 8) * APAD + nt * 8 + 2 * qc] = make_float2(tf32f(p10), tf32f(p11));
        }
        __syncwarp();

#pragma unroll
        for (int ks = 0; ks < 8; ks++) {
            unsigned a[4] = {
                __float_as_uint(Ps[m0 * APAD + ks * 8 + qc]),
                __float_as_uint(Ps[(m0 + 8) * APAD + ks * 8 + qc]),
                __float_as_uint(Ps[m0 * APAD + ks * 8 + qc + 4]),
                __float_as_uint(Ps[(m0 + 8) * APAD + ks * 8 + qc + 4])
            };
#pragma unroll
            for (int nt = 0; nt < 8; nt++) {
                const int n = nt * 8 + qr;
                unsigned b[2] = {
                    __float_as_uint(Vs[(ks * 8 + qc) * APAD + n]),
                    __float_as_uint(Vs[(ks * 8 + qc + 4) * APAD + n])
                };
                mma_tf32(oacc[nt], a, b);
            }
        }
        __syncwarp();
    }

    rs0 += __shfl_xor_sync(0xffffffffu, rs0, 1);
    rs0 += __shfl_xor_sync(0xffffffffu, rs0, 2);
    rs1 += __shfl_xor_sync(0xffffffffu, rs1, 1);
    rs1 += __shfl_xor_sync(0xffffffffu, rs1, 2);
    const float inv0 = 1.f / rs0;
    const float inv1 = 1.f / rs1;

#pragma unroll
    for (int nt = 0; nt < 8; nt++) {
        const int col = h * HEAD_DIM + nt * 8 + 2 * qc;
        *(__half2*)(Oh + (size_t)i0 * D_MODEL + col) =
            __floats2half2_rn(oacc[nt][0] * inv0, oacc[nt][1] * inv0);
        *(__half2*)(Oh + (size_t)i1 * D_MODEL + col) =
            __floats2half2_rn(oacc[nt][2] * inv1, oacc[nt][3] * inv1);
    }
}

// ---------------------------------------------------------------------------
// Launch
// ---------------------------------------------------------------------------
extern "C" void kernel_launch(void* const* d_in, const int* in_sizes, int n_in,
                              void* d_out, int out_size)
{
    const float* X  = (const float*)d_in[0];
    const float* Wq = (const float*)d_in[1];
    const float* Wk = (const float*)d_in[2];
    const float* Wv = (const float*)d_in[3];
    const float* Wo = (const float*)d_in[4];
    float* out = (float*)d_out;

    float* Qb;  cudaGetSymbolAddress((void**)&Qb, g_Q);
    float* Kb;  cudaGetSymbolAddress((void**)&Kb, g_K);
    float* Vb;  cudaGetSymbolAddress((void**)&Vb, g_V);
    __half *Xh, *Wh, *Wl, *Woh, *Wol, *Oh;
    cudaGetSymbolAddress((void**)&Xh,  g_Xh);
    cudaGetSymbolAddress((void**)&Wh,  g_Wh);
    cudaGetSymbolAddress((void**)&Wl,  g_Wl);
    cudaGetSymbolAddress((void**)&Woh, g_Woh);
    cudaGetSymbolAddress((void**)&Wol, g_Wol);
    cudaGetSymbolAddress((void**)&Oh,  g_Oh);

    static bool attr_set = false;
    if (!attr_set) {
        cudaFuncSetAttribute(gemm_fp2, cudaFuncAttributeMaxDynamicSharedMemorySize, GEMM_SMEM);
        cudaFuncSetAttribute(attn_mma, cudaFuncAttributeMaxDynamicSharedMemorySize, ATTN_SMEM);
        attr_set = true;
    }

    split_all<<<(N4_TOT + 255) / 256, 256>>>(X, Wq, Wk, Wv, Wo, Xh, Wh, Wl, Woh, Wol);
    rope_tables<<<(T_SEQ * 32 + 255) / 256, 256>>>();

    gemm_fp2<<<dim3(QKV_N / BN, T_SEQ / BM), 256, GEMM_SMEM>>>(
        Xh, Wh, Wl, D_MODEL,
        Qb, D_MODEL, D_MODEL,
        Kb, D_MODEL + KV_DIM, KV_DIM,
        Vb, KV_DIM);

    attn_mma<<<dim3(T_SEQ / QT, N_HEADS), 128, ATTN_SMEM>>>(Qb, Kb, Vb, Oh);

    gemm_fp2<<<dim3(D_MODEL / BN, T_SEQ / BM), 256, GEMM_SMEM>>>(
        Oh, Woh, Wol, D_MODEL,
        out, D_MODEL, D_MODEL,
        out, D_MODEL + 1, D_MODEL,
        out, D_MODEL);
}

// round 9
// speedup vs baseline: 6.5052x; 1.2851x over previous
#include <cuda_runtime.h>
#include <cuda_fp16.h>
#include <math.h>
#include <stdint.h>

// ---------------------------------------------------------------------------
// Problem constants
// ---------------------------------------------------------------------------
#define T_SEQ    2048
#define D_MODEL  2048
#define N_HEADS  32
#define N_KV     8
#define HEAD_DIM 64
#define KV_DIM   (N_KV * HEAD_DIM)       // 512
#define QKV_N    (D_MODEL + 2 * KV_DIM)  // 3072
#define WINDOW_HALF 256

// ---------------------------------------------------------------------------
// Scratch (device globals; no allocation allowed)
// ---------------------------------------------------------------------------
__device__ float  g_Q[(size_t)T_SEQ * D_MODEL];
__device__ float  g_K[(size_t)T_SEQ * KV_DIM];
__device__ float  g_V[(size_t)T_SEQ * KV_DIM];
__device__ __half g_Xh[(size_t)T_SEQ * D_MODEL];
__device__ __half g_Wh[(size_t)QKV_N * D_MODEL];
__device__ __half g_Wl[(size_t)QKV_N * D_MODEL];
__device__ __half g_Woh[(size_t)D_MODEL * D_MODEL];
__device__ __half g_Oh[(size_t)T_SEQ * D_MODEL];
__device__ float  g_cos[T_SEQ * 32];
__device__ float  g_sin[T_SEQ * 32];

// ---------------------------------------------------------------------------
// helpers
// ---------------------------------------------------------------------------
__device__ __forceinline__ unsigned smem_u32(const void* p)
{
    unsigned a;
    asm("{ .reg .u64 t; cvta.to.shared.u64 t, %1; cvt.u32.u64 %0, t; }" : "=r"(a) : "l"(p));
    return a;
}

__device__ __forceinline__ void mma_fp16(float* c, const unsigned* a, const unsigned* b)
{
    asm volatile(
        "mma.sync.aligned.m16n8k16.row.col.f32.f16.f16.f32 "
        "{%0,%1,%2,%3}, {%4,%5,%6,%7}, {%8,%9}, {%0,%1,%2,%3};"
        : "+f"(c[0]), "+f"(c[1]), "+f"(c[2]), "+f"(c[3])
        : "r"(a[0]), "r"(a[1]), "r"(a[2]), "r"(a[3]),
          "r"(b[0]), "r"(b[1]));
}

__device__ __forceinline__ void ldsm_x4(unsigned* r, unsigned addr)
{
    asm volatile("ldmatrix.sync.aligned.m8n8.x4.shared.b16 {%0,%1,%2,%3}, [%4];"
                 : "=r"(r[0]), "=r"(r[1]), "=r"(r[2]), "=r"(r[3]) : "r"(addr));
}

__device__ __forceinline__ void ldsm_x4_t(unsigned* r, unsigned addr)
{
    asm volatile("ldmatrix.sync.aligned.m8n8.x4.trans.shared.b16 {%0,%1,%2,%3}, [%4];"
                 : "=r"(r[0]), "=r"(r[1]), "=r"(r[2]), "=r"(r[3]) : "r"(addr));
}

__device__ __forceinline__ void cp16(unsigned dst, const void* src)
{
    asm volatile("cp.async.ca.shared.global [%0], [%1], 16;" :: "r"(dst), "l"(src));
}

// ---------------------------------------------------------------------------
// Fused split: X -> fp16; Wq/Wk/Wv -> fp16 hi/lo; Wo -> fp16 hi only.
// ---------------------------------------------------------------------------
#define N4_X   (T_SEQ * D_MODEL / 4)
#define N4_WQ  (D_MODEL * D_MODEL / 4)
#define N4_WKV (KV_DIM * D_MODEL / 4)
#define N4_WO  (D_MODEL * D_MODEL / 4)
#define N4_TOT (N4_X + N4_WQ + 2 * N4_WKV + N4_WO)

__global__ void split_all(const float* __restrict__ X,  const float* __restrict__ Wq,
                          const float* __restrict__ Wk, const float* __restrict__ Wv,
                          const float* __restrict__ Wo,
                          __half* __restrict__ Xh,
                          __half* __restrict__ Wh, __half* __restrict__ Wl,
                          __half* __restrict__ Woh)
{
    int i = blockIdx.x * blockDim.x + threadIdx.x;
    if (i >= N4_TOT) return;

    const float* s; __half *hp, *lp = 0; int off; bool has_lo = false;
    if (i < N4_X)                         { off = i;                           s = X;  hp = Xh; }
    else if (i < N4_X + N4_WQ)            { off = i - N4_X;                    s = Wq; hp = Wh; lp = Wl; has_lo = true; }
    else if (i < N4_X + N4_WQ + N4_WKV)   { off = i - N4_X - N4_WQ;            s = Wk;
                                            hp = Wh + (size_t)D_MODEL * D_MODEL;
                                            lp = Wl + (size_t)D_MODEL * D_MODEL; has_lo = true; }
    else if (i < N4_X + N4_WQ + 2*N4_WKV) { off = i - N4_X - N4_WQ - N4_WKV;   s = Wv;
                                            hp = Wh + (size_t)(D_MODEL + KV_DIM) * D_MODEL;
                                            lp = Wl + (size_t)(D_MODEL + KV_DIM) * D_MODEL; has_lo = true; }
    else                                  { off = i - N4_X - N4_WQ - 2*N4_WKV; s = Wo; hp = Woh; }

    float4 v = ((const float4*)s)[off];
    float x[4] = {v.x, v.y, v.z, v.w};
    __half h[4], l[4];
#pragma unroll
    for (int j = 0; j < 4; j++) {
        h[j] = __float2half_rn(x[j]);
        l[j] = __float2half_rn(x[j] - __half2float(h[j]));
    }
    __half2* hq = (__half2*)hp;
    hq[2 * off]     = __halves2half2(h[0], h[1]);
    hq[2 * off + 1] = __halves2half2(h[2], h[3]);
    if (has_lo) {
        __half2* lq = (__half2*)lp;
        lq[2 * off]     = __halves2half2(l[0], l[1]);
        lq[2 * off + 1] = __halves2half2(l[2], l[3]);
    }
}

// ---------------------------------------------------------------------------
// fp16 tensor-core GEMM, NPASS passes over B planes (2 = hi/lo split, 1 = hi).
//   C[M,N] = A[M,K] * B[N,K]^T
// Block 128x128x32, 256 thr, warp tile 64x32, 2-stage cp.async, ldmatrix.
// ---------------------------------------------------------------------------
#define BM 128
#define BN 128
#define GBK 32
#define KPAD 40
#define PLANE_E (128 * KPAD)
#define PLANE_BYTES (PLANE_E * 2)        // 10240
#define STAGE_B (3 * PLANE_BYTES)        // 30720 (layout fixed at 3 planes)
#define GEMM_SMEM (2 * STAGE_B)          // 61440

template<int NPLANES>
__device__ __forceinline__ void stage_fp(unsigned sbase,
                                         const __half* A, const __half* Bh, const __half* Bl,
                                         int K, int bm, int bn, int k0, int tid)
{
#pragma unroll
    for (int t = 0; t < 2 * NPLANES; t++) {
        int id = tid + t * 256;
        int plane = id >> 9;                 // 0..NPLANES-1
        int r = (id >> 2) & 127;
        int c = id & 3;
        unsigned dst = sbase + (unsigned)(plane * PLANE_E + r * KPAD + c * 8) * 2u;
        const __half* src;
        if (plane == 0)      src = A  + (size_t)(bm + r) * K + k0 + c * 8;
        else if (plane == 1) src = Bh + (size_t)(bn + r) * K + k0 + c * 8;
        else                 src = Bl + (size_t)(bn + r) * K + k0 + c * 8;
        cp16(dst, src);
    }
}

template<int NPASS>
__global__ void __launch_bounds__(256, 2)
gemm_fp(const __half* __restrict__ A, const __half* __restrict__ Bh,
        const __half* __restrict__ Bl, int K,
        float* __restrict__ C0, int n0, int s0,
        float* __restrict__ C1, int n1, int s1,
        float* __restrict__ C2, int s2)
{
    extern __shared__ __half smb[];
    unsigned sbase = smem_u32(smb);

    const int tid = threadIdx.x;
    const int bm = blockIdx.y * BM;
    const int bn = blockIdx.x * BN;

    const int warp = tid >> 5;
    const int lane = tid & 31;
    const int qr = lane >> 2;
    const int qc = lane & 3;
    const int wr = warp >> 2;
    const int wc = warp & 3;

    const int lane8 = lane & 7;
    const int mat   = lane >> 3;
    const unsigned a_e = (unsigned)((wr * 64 + (mat & 1) * 8 + lane8) * KPAD + (mat >> 1) * 8);
    const unsigned b_e = (unsigned)((wc * 32 + (mat & 1) * 8 + lane8) * KPAD + (mat >> 1) * 8);

    float acc[4][4][4];
#pragma unroll
    for (int i = 0; i < 4; i++)
#pragma unroll
        for (int j = 0; j < 4; j++)
#pragma unroll
            for (int r = 0; r < 4; r++) acc[i][j][r] = 0.f;

    const int NS = K / GBK;

    stage_fp<NPASS + 1>(sbase, A, Bh, Bl, K, bm, bn, 0, tid);
    asm volatile("cp.async.commit_group;" ::: "memory");
    stage_fp<NPASS + 1>(sbase + STAGE_B, A, Bh, Bl, K, bm, bn, GBK, tid);
    asm volatile("cp.async.commit_group;" ::: "memory");

    for (int s = 0; s < NS; s++) {
        asm volatile("cp.async.wait_group 1;" ::: "memory");
        __syncthreads();

        const int buf = s & 1;
        const unsigned stg = sbase + buf * STAGE_B;
        const unsigned aP = stg + a_e * 2;
        const unsigned bH = stg + PLANE_BYTES + b_e * 2;
        const unsigned bL = bH + PLANE_BYTES;

#pragma unroll
        for (int ks = 0; ks < GBK; ks += 16) {
            unsigned bh[2][4], bl[2][4];
#pragma unroll
            for (int n2 = 0; n2 < 2; n2++) {
                ldsm_x4(bh[n2], bH + n2 * (16 * KPAD * 2) + ks * 2);
                if (NPASS == 2) ldsm_x4(bl[n2], bL + n2 * (16 * KPAD * 2) + ks * 2);
            }
#pragma unroll
            for (int mt = 0; mt < 4; mt++) {
                unsigned ah[4];
                ldsm_x4(ah, aP + mt * (16 * KPAD * 2) + ks * 2);
#pragma unroll
                for (int nt = 0; nt < 4; nt++) {
                    const int n2 = nt >> 1, od = nt & 1;
                    unsigned bhf[2] = {bh[n2][od], bh[n2][od + 2]};
                    mma_fp16(acc[mt][nt], ah, bhf);
                    if (NPASS == 2) {
                        unsigned blf[2] = {bl[n2][od], bl[n2][od + 2]};
                        mma_fp16(acc[mt][nt], ah, blf);
                    }
                }
            }
        }
        __syncthreads();

        if (s + 2 < NS)
            stage_fp<NPASS + 1>(sbase + buf * STAGE_B, A, Bh, Bl, K, bm, bn, (s + 2) * GBK, tid);
        asm volatile("cp.async.commit_group;" ::: "memory");
    }

    float* C; int col0, stride;
    if (bn < n0)      { C = C0; col0 = bn;      stride = s0; }
    else if (bn < n1) { C = C1; col0 = bn - n0; stride = s1; }
    else              { C = C2; col0 = bn - n1; stride = s2; }

#pragma unroll
    for (int mt = 0; mt < 4; mt++) {
        const int row0 = bm + wr * 64 + mt * 16 + qr;
#pragma unroll
        for (int nt = 0; nt < 4; nt++) {
            const int col = col0 + wc * 32 + nt * 8 + qc * 2;
            *(float2*)(C + (size_t)row0       * stride + col) = make_float2(acc[mt][nt][0], acc[mt][nt][1]);
            *(float2*)(C + (size_t)(row0 + 8) * stride + col) = make_float2(acc[mt][nt][2], acc[mt][nt][3]);
        }
    }
}

// ---------------------------------------------------------------------------
// RoPE tables
// ---------------------------------------------------------------------------
__global__ void rope_tables()
{
    int idx = blockIdx.x * blockDim.x + threadIdx.x;
    if (idx >= T_SEQ * 32) return;
    int i = idx & 31;
    int t = idx >> 5;
    double invf = exp2(-(double)i / 32.0 * 13.287712379549449392);
    double ang  = fmod((double)t * invf, 6.28318530717958647692);
    g_cos[idx] = cosf((float)ang);
    g_sin[idx] = sinf((float)ang);
}

// ---------------------------------------------------------------------------
// fp16 tensor-core banded GQA attention with fused RoPE.
// Block = 64-query tile x 1 head, 128 threads (4 warps x 16 q-rows).
// fp16 smem staging (static, 27.6 KB), mma.m16n8k16, ldmatrix fragments,
// V consumed via ldmatrix.trans from [j][d] layout.
// ---------------------------------------------------------------------------
#define QT  64
#define CHK 64
#define AP  72   // fp16 elems per row (64 + 8 pad); 144B rows, 16B-aligned

__global__ void __launch_bounds__(128)
attn_fp16(const float* __restrict__ Q, const float* __restrict__ K,
          const float* __restrict__ V, __half* __restrict__ Oh)
{
    __shared__ __half sm[3 * QT * AP];
    __half* Qs = sm;                 // reused as Ps after Q-frag hoist
    __half* Ks = sm + QT * AP;
    __half* Vs = sm + 2 * QT * AP;
    const unsigned sQ = smem_u32(Qs);
    const unsigned sK = smem_u32(Ks);
    const unsigned sV = smem_u32(Vs);

    const int h  = blockIdx.y;
    const int g  = h >> 2;
    const int q0 = blockIdx.x * QT;
    const int tid = threadIdx.x;
    const int w = tid >> 5;
    const int lane = tid & 31;
    const int qr = lane >> 2;
    const int qc = lane & 3;
    const int lane8 = lane & 7;
    const int mat   = lane >> 3;

    // ldmatrix element offsets
    const unsigned q_e = (unsigned)((w * 16 + (mat & 1) * 8 + lane8) * AP + (mat >> 1) * 8);
    const unsigned k_e = (unsigned)(((mat & 1) * 8 + lane8) * AP + (mat >> 1) * 8);
    const unsigned v_e = (unsigned)(((mat >> 1) * 8 + lane8) * AP + (mat & 1) * 8);

    // stage Q tile with RoPE (pairs d, d+32) as fp16
#pragma unroll
    for (int t = 0; t < 4; t++) {
        int idx = tid + t * 128;
        int r  = idx >> 3;
        int d4 = (idx & 7) * 4;
        const float* qp = Q + (size_t)(q0 + r) * D_MODEL + h * HEAD_DIM;
        float4 a  = *(const float4*)(qp + d4);
        float4 b  = *(const float4*)(qp + d4 + 32);
        float4 cs = *(const float4*)(g_cos + (q0 + r) * 32 + d4);
        float4 sn = *(const float4*)(g_sin + (q0 + r) * 32 + d4);
        *(__half2*)&Qs[r * AP + d4]      = __floats2half2_rn(a.x * cs.x - b.x * sn.x, a.y * cs.y - b.y * sn.y);
        *(__half2*)&Qs[r * AP + d4 + 2]  = __floats2half2_rn(a.z * cs.z - b.z * sn.z, a.w * cs.w - b.w * sn.w);
        *(__half2*)&Qs[r * AP + d4 + 32] = __floats2half2_rn(b.x * cs.x + a.x * sn.x, b.y * cs.y + a.y * sn.y);
        *(__half2*)&Qs[r * AP + d4 + 34] = __floats2half2_rn(b.z * cs.z + a.z * sn.z, b.w * cs.w + a.w * sn.w);
    }
    __syncthreads();

    // hoist Q A-fragments for all 4 k-steps
    unsigned qa[4][4];
#pragma unroll
    for (int ks = 0; ks < 4; ks++)
        ldsm_x4(qa[ks], sQ + (q_e + ks * 16) * 2);
    __syncthreads();          // everyone done reading Q before Ps overwrite

    float oacc[8][4];
#pragma unroll
    for (int nt = 0; nt < 8; nt++)
#pragma unroll
        for (int r = 0; r < 4; r++) oacc[nt][r] = 0.f;
    float rs0 = 0.f, rs1 = 0.f;

    const int i0 = q0 + w * 16 + qr;
    const int i1 = i0 + 8;
    const int m0 = w * 16 + qr;
    const float SC = 0.125f * 1.44269504088896f;

    const int jstart = max(0, q0 - WINDOW_HALF);
    const int jend   = min(T_SEQ, q0 + QT + WINDOW_HALF);

    for (int c = jstart; c < jend; c += CHK) {
        __syncthreads();
        // stage K (RoPE) + V as fp16
#pragma unroll
        for (int t = 0; t < 2; t++) {
            int idx = tid + t * 128;
            int r  = idx >> 2;
            int d8 = (idx & 3) * 8;
#pragma unroll
            for (int hlf = 0; hlf < 2; hlf++) {
                int d = d8 + hlf * 4;
                const size_t go = (size_t)(c + r) * KV_DIM + g * HEAD_DIM + d;
                float4 a  = *(const float4*)(K + go);
                float4 b  = *(const float4*)(K + go + 32);
                float4 cs = *(const float4*)(g_cos + (c + r) * 32 + d);
                float4 sn = *(const float4*)(g_sin + (c + r) * 32 + d);
                *(__half2*)&Ks[r * AP + d]      = __floats2half2_rn(a.x * cs.x - b.x * sn.x, a.y * cs.y - b.y * sn.y);
                *(__half2*)&Ks[r * AP + d + 2]  = __floats2half2_rn(a.z * cs.z - b.z * sn.z, a.w * cs.w - b.w * sn.w);
                *(__half2*)&Ks[r * AP + d + 32] = __floats2half2_rn(b.x * cs.x + a.x * sn.x, b.y * cs.y + a.y * sn.y);
                *(__half2*)&Ks[r * AP + d + 34] = __floats2half2_rn(b.z * cs.z + a.z * sn.z, b.w * cs.w + a.w * sn.w);
                float4 v0 = *(const float4*)(V + go);
                float4 v1 = *(const float4*)(V + go + 32);
                *(__half2*)&Vs[r * AP + d]      = __floats2half2_rn(v0.x, v0.y);
                *(__half2*)&Vs[r * AP + d + 2]  = __floats2half2_rn(v0.z, v0.w);
                *(__half2*)&Vs[r * AP + d + 32] = __floats2half2_rn(v1.x, v1.y);
                *(__half2*)&Vs[r * AP + d + 34] = __floats2half2_rn(v1.z, v1.w);
            }
        }
        __syncthreads();

        // S = Q K^T : 8 n-tiles x 4 k-steps, fp16 mma
        float sfr[8][4];
#pragma unroll
        for (int nt = 0; nt < 8; nt++)
#pragma unroll
            for (int r = 0; r < 4; r++) sfr[nt][r] = 0.f;
#pragma unroll
        for (int ks = 0; ks < 4; ks++) {
            unsigned kb[4][4];
#pragma unroll
            for (int n2 = 0; n2 < 4; n2++)
                ldsm_x4(kb[n2], sK + (k_e + n2 * 16 * AP + ks * 16) * 2);
#pragma unroll
            for (int nt = 0; nt < 8; nt++) {
                const int n2 = nt >> 1, od = nt & 1;
                unsigned bf[2] = {kb[n2][od], kb[n2][od + 2]};
                mma_fp16(sfr[nt], qa[ks], bf);
            }
        }

        // mask + exp + rowsum + store P (fp16) to warp-private Ps rows
#pragma unroll
        for (int nt = 0; nt < 8; nt++) {
            const int j0 = c + nt * 8 + 2 * qc;
            const int j1 = j0 + 1;
            float p00 = (j0 >= i0 - WINDOW_HALF && j0 < i0 + WINDOW_HALF) ? exp2f(sfr[nt][0] * SC) : 0.f;
            float p01 = (j1 >= i0 - WINDOW_HALF && j1 < i0 + WINDOW_HALF) ? exp2f(sfr[nt][1] * SC) : 0.f;
            float p10 = (j0 >= i1 - WINDOW_HALF && j0 < i1 + WINDOW_HALF) ? exp2f(sfr[nt][2] * SC) : 0.f;
            float p11 = (j1 >= i1 - WINDOW_HALF && j1 < i1 + WINDOW_HALF) ? exp2f(sfr[nt][3] * SC) : 0.f;
            rs0 += p00 + p01;
            rs1 += p10 + p11;
            *(__half2*)&Qs[m0 * AP + nt * 8 + 2 * qc]       = __floats2half2_rn(p00, p01);
            *(__half2*)&Qs[(m0 + 8) * AP + nt * 8 + 2 * qc] = __floats2half2_rn(p10, p11);
        }
        __syncwarp();

        // O += P V : A from Ps, B from Vs via ldmatrix.trans
#pragma unroll
        for (int ks = 0; ks < 4; ks++) {
            unsigned pa[4];
            ldsm_x4(pa, sQ + (q_e + ks * 16) * 2);
            unsigned vb[4][4];
#pragma unroll
            for (int n2 = 0; n2 < 4; n2++)
                ldsm_x4_t(vb[n2], sV + (v_e + ks * 16 * AP + n2 * 16) * 2);
#pragma unroll
            for (int nt = 0; nt < 8; nt++) {
                const int n2 = nt >> 1, od = nt & 1;
                unsigned bf[2] = {vb[n2][od], vb[n2][od + 2]};
                mma_fp16(oacc[nt], pa, bf);
            }
        }
        __syncwarp();
    }

    rs0 += __shfl_xor_sync(0xffffffffu, rs0, 1);
    rs0 += __shfl_xor_sync(0xffffffffu, rs0, 2);
    rs1 += __shfl_xor_sync(0xffffffffu, rs1, 1);
    rs1 += __shfl_xor_sync(0xffffffffu, rs1, 2);
    const float inv0 = 1.f / rs0;
    const float inv1 = 1.f / rs1;

#pragma unroll
    for (int nt = 0; nt < 8; nt++) {
        const int col = h * HEAD_DIM + nt * 8 + 2 * qc;
        *(__half2*)(Oh + (size_t)i0 * D_MODEL + col) =
            __floats2half2_rn(oacc[nt][0] * inv0, oacc[nt][1] * inv0);
        *(__half2*)(Oh + (size_t)i1 * D_MODEL + col) =
            __floats2half2_rn(oacc[nt][2] * inv1, oacc[nt][3] * inv1);
    }
}

// ---------------------------------------------------------------------------
// Launch
// ---------------------------------------------------------------------------
extern "C" void kernel_launch(void* const* d_in, const int* in_sizes, int n_in,
                              void* d_out, int out_size)
{
    const float* X  = (const float*)d_in[0];
    const float* Wq = (const float*)d_in[1];
    const float* Wk = (const float*)d_in[2];
    const float* Wv = (const float*)d_in[3];
    const float* Wo = (const float*)d_in[4];
    float* out = (float*)d_out;

    float* Qb;  cudaGetSymbolAddress((void**)&Qb, g_Q);
    float* Kb;  cudaGetSymbolAddress((void**)&Kb, g_K);
    float* Vb;  cudaGetSymbolAddress((void**)&Vb, g_V);
    __half *Xh, *Wh, *Wl, *Woh, *Oh;
    cudaGetSymbolAddress((void**)&Xh,  g_Xh);
    cudaGetSymbolAddress((void**)&Wh,  g_Wh);
    cudaGetSymbolAddress((void**)&Wl,  g_Wl);
    cudaGetSymbolAddress((void**)&Woh, g_Woh);
    cudaGetSymbolAddress((void**)&Oh,  g_Oh);

    static bool attr_set = false;
    if (!attr_set) {
        cudaFuncSetAttribute(gemm_fp<2>, cudaFuncAttributeMaxDynamicSharedMemorySize, GEMM_SMEM);
        cudaFuncSetAttribute(gemm_fp<1>, cudaFuncAttributeMaxDynamicSharedMemorySize, GEMM_SMEM);
        attr_set = true;
    }

    split_all<<<(N4_TOT + 255) / 256, 256>>>(X, Wq, Wk, Wv, Wo, Xh, Wh, Wl, Woh);
    rope_tables<<<(T_SEQ * 32 + 255) / 256, 256>>>();

    gemm_fp<2><<<dim3(QKV_N / BN, T_SEQ / BM), 256, GEMM_SMEM>>>(
        Xh, Wh, Wl, D_MODEL,
        Qb, D_MODEL, D_MODEL,
        Kb, D_MODEL + KV_DIM, KV_DIM,
        Vb, KV_DIM);

    attn_fp16<<<dim3(T_SEQ / QT, N_HEADS), 128>>>(Qb, Kb, Vb, Oh);

    gemm_fp<1><<<dim3(D_MODEL / BN, T_SEQ / BM), 256, GEMM_SMEM>>>(
        Oh, Woh, Woh, D_MODEL,
        out, D_MODEL, D_MODEL,
        out, D_MODEL + 1, D_MODEL,
        out, D_MODEL);
}